// round 5
// baseline (speedup 1.0000x reference)
#include <cuda_runtime.h>
#include <cuda_fp16.h>
#include <cstdint>
#include <math.h>

// ---------------- problem constants ----------------
#define HID    2048
#define BROWS  4096
#define KHALF  2048           // K extent of each half (x/Wx vs hx/Wh)

constexpr int BM = 128;       // rows per CTA
constexpr int BN = 128;       // C cols per CTA (col = h*4 + g -> 32 hidden cols)
constexpr int BK = 32;        // K per smem tile (2 mma k16 steps)
constexpr int NT = 4096 / BK;        // 128 k-tiles
constexpr int HALF_T = 2048 / BK;    // 64
constexpr int NUM_NT = (4 * HID) / BN;  // 64 n-tiles
constexpr int GROUP_M = 8;

// ---------------- smem layout ----------------
// fp16 tiles: 128 rows x 32 fp16, padded row stride 80 bytes (conflict-free:
// bank(r,t) = (20r + t) mod 32 is a bijection over the fragment pattern)
constexpr int SROW = 80;                     // bytes per tile row
constexpr int TILE_B = BM * SROW;            // 10240 B
constexpr int SM_A0 = 1024;
constexpr int SM_A1 = SM_A0 + TILE_B;
constexpr int SM_B0 = SM_A1 + TILE_B;
constexpr int SM_B1 = SM_B0 + TILE_B;        // ends at 41984
constexpr int CSTRIDE = 132;                 // epilogue C stride (floats)
constexpr int SM_C = 1024;                   // epilogue reuses tile region
constexpr int SMEM_TOTAL = 1024 + BM * CSTRIDE * 4;  // 68608

__device__ __forceinline__ float sigm(float v) { return 1.f / (1.f + __expf(-v)); }

__device__ __forceinline__ uint32_t h2u(__half2 h) { return *(uint32_t*)&h; }

__device__ __forceinline__ void mma_f16(float& c0, float& c1, float& c2, float& c3,
                                        uint32_t a0, uint32_t a1, uint32_t a2, uint32_t a3,
                                        uint32_t b0, uint32_t b1) {
    asm volatile(
        "mma.sync.aligned.m16n8k16.row.col.f32.f16.f16.f32 "
        "{%0,%1,%2,%3}, {%4,%5,%6,%7}, {%8,%9}, {%0,%1,%2,%3};"
        : "+f"(c0), "+f"(c1), "+f"(c2), "+f"(c3)
        : "r"(a0), "r"(a1), "r"(a2), "r"(a3), "r"(b0), "r"(b1));
}

// ---------------- kernel ----------------
__global__ __launch_bounds__(256, 1)
void lstm_mma_fp16_kernel(const float* __restrict__ x,
                          const float* __restrict__ hx,
                          const float* __restrict__ cx,
                          const float* __restrict__ Wx,
                          const float* __restrict__ bx,
                          const float* __restrict__ Wh,
                          const float* __restrict__ bh,
                          float* __restrict__ out)
{
    extern __shared__ __align__(1024) uint8_t smem[];
    const int tid  = threadIdx.x;
    const int wid  = tid >> 5;
    const int lane = tid & 31;
    const int g    = lane >> 2;   // group id (0..7)
    const int tig  = lane & 3;    // thread in group

    // ---- CTA tile mapping (GROUP_M swizzle for L2 reuse of W) ----
    int bid    = blockIdx.x;
    int group  = bid / (GROUP_M * NUM_NT);
    int rem    = bid % (GROUP_M * NUM_NT);
    int m_tile = group * GROUP_M + (rem % GROUP_M);
    int n_tile = rem / GROUP_M;
    const int m0 = m_tile * BM;
    const int j0 = n_tile * (BN / 4);   // 32 hidden cols per CTA

    // ---- per-thread load/store descriptors ----
    // thread covers tile row (t&127) and 16 consecutive k at offset (t>>7)*16
    const int lrow = tid & 127;
    const int kh   = tid >> 7;          // 0/1
    const size_t a_src = (size_t)(m0 + lrow) * KHALF + kh * 16;
    const int gg = lrow & 3, jl = lrow >> 2;
    const size_t b_src = (size_t)(gg * HID + j0 + jl) * KHALF + kh * 16;
    const uint32_t sts_o = (uint32_t)(lrow * SROW + kh * 32);  // byte offset in tile

    const int smA[2] = {SM_A0, SM_A1};
    const int smB[2] = {SM_B0, SM_B1};

    auto ldg_tile = [&](int t, float4* A, float4* Bv) {
        const float* ap = (t < HALF_T) ? x  : hx;
        const float* wp = (t < HALF_T) ? Wx : Wh;
        const int kofs  = ((t < HALF_T) ? t : (t - HALF_T)) * BK;
#pragma unroll
        for (int i = 0; i < 4; i++) {
            A[i]  = *(const float4*)(ap + a_src + kofs + i * 4);
            Bv[i] = *(const float4*)(wp + b_src + kofs + i * 4);
        }
    };
    auto sts_tile = [&](int buf, const float4* A, const float4* Bv) {
        // 16 floats -> 16 fp16 -> two 16B chunks per operand
#pragma unroll
        for (int c = 0; c < 2; c++) {
            uint4 va, vb;
            va.x = h2u(__floats2half2_rn(A[c*2].x,   A[c*2].y));
            va.y = h2u(__floats2half2_rn(A[c*2].z,   A[c*2].w));
            va.z = h2u(__floats2half2_rn(A[c*2+1].x, A[c*2+1].y));
            va.w = h2u(__floats2half2_rn(A[c*2+1].z, A[c*2+1].w));
            vb.x = h2u(__floats2half2_rn(Bv[c*2].x,   Bv[c*2].y));
            vb.y = h2u(__floats2half2_rn(Bv[c*2].z,   Bv[c*2].w));
            vb.z = h2u(__floats2half2_rn(Bv[c*2+1].x, Bv[c*2+1].y));
            vb.w = h2u(__floats2half2_rn(Bv[c*2+1].z, Bv[c*2+1].w));
            *(uint4*)(smem + smA[buf] + sts_o + c * 16) = va;
            *(uint4*)(smem + smB[buf] + sts_o + c * 16) = vb;
        }
    };

    // ---- warp tile: 2(M) x 4(N), 64x32 per warp ----
    const int wm = (wid >> 2) * 64;
    const int wn = (wid & 3) * 32;

    float acc[4][4][4];
#pragma unroll
    for (int mi = 0; mi < 4; mi++)
#pragma unroll
        for (int ni = 0; ni < 4; ni++)
#pragma unroll
            for (int q = 0; q < 4; q++) acc[mi][ni][q] = 0.f;

    // ---- prologue ----
    float4 stgA[4], stgB[4];
    ldg_tile(0, stgA, stgB);
    sts_tile(0, stgA, stgB);
    __syncthreads();

    // ---- mainloop ----
    for (int t = 0; t < NT; t++) {
        const int buf = t & 1;
        if (t + 1 < NT) ldg_tile(t + 1, stgA, stgB);

        const uint8_t* At = smem + smA[buf];
        const uint8_t* Bt = smem + smB[buf];

#pragma unroll
        for (int kk = 0; kk < 2; kk++) {
            const int kb = kk * 32 + tig * 4;       // byte offset: k pair 2*tig (+ k16 block)
            uint32_t a[4][4], b[4][2];
#pragma unroll
            for (int mi = 0; mi < 4; mi++) {
                const int r1 = wm + mi * 16 + g;
                a[mi][0] = *(const uint32_t*)(At + (r1)     * SROW + kb);
                a[mi][1] = *(const uint32_t*)(At + (r1 + 8) * SROW + kb);
                a[mi][2] = *(const uint32_t*)(At + (r1)     * SROW + kb + 16);
                a[mi][3] = *(const uint32_t*)(At + (r1 + 8) * SROW + kb + 16);
            }
#pragma unroll
            for (int ni = 0; ni < 4; ni++) {
                const int c = wn + ni * 8 + g;
                b[ni][0] = *(const uint32_t*)(Bt + c * SROW + kb);
                b[ni][1] = *(const uint32_t*)(Bt + c * SROW + kb + 16);
            }
#pragma unroll
            for (int mi = 0; mi < 4; mi++)
#pragma unroll
                for (int ni = 0; ni < 4; ni++)
                    mma_f16(acc[mi][ni][0], acc[mi][ni][1], acc[mi][ni][2], acc[mi][ni][3],
                            a[mi][0], a[mi][1], a[mi][2], a[mi][3],
                            b[ni][0], b[ni][1]);
        }

        if (t + 1 < NT) {
            sts_tile(buf ^ 1, stgA, stgB);
            __syncthreads();
        }
    }

    // ---- epilogue: stage C through smem, then fused LSTM math ----
    __syncthreads();   // all warps done reading A/B tiles
    float* Cs = (float*)(smem + SM_C);
#pragma unroll
    for (int mi = 0; mi < 4; mi++) {
#pragma unroll
        for (int ni = 0; ni < 4; ni++) {
            const int r1 = wm + mi * 16 + g;
            const int c0 = wn + ni * 8 + tig * 2;
            *(float2*)(Cs + r1 * CSTRIDE + c0)       = make_float2(acc[mi][ni][0], acc[mi][ni][1]);
            *(float2*)(Cs + (r1 + 8) * CSTRIDE + c0) = make_float2(acc[mi][ni][2], acc[mi][ni][3]);
        }
    }
    __syncthreads();

    // biases for this thread's hidden column (h = lane)
    const int j = j0 + lane;
    const float bs0 = bx[0 * HID + j] + bh[0 * HID + j];
    const float bs1 = bx[1 * HID + j] + bh[1 * HID + j];
    const float bs2 = bx[2 * HID + j] + bh[2 * HID + j];
    const float bs3 = bx[3 * HID + j] + bh[3 * HID + j];

#pragma unroll
    for (int i = 0; i < 16; i++) {
        const int rl  = i * 8 + wid;          // local row 0..127
        const int row = m0 + rl;
        const float4 gv = *(const float4*)(Cs + rl * CSTRIDE + lane * 4);
        const float f_ = sigm (gv.x + bs0);
        const float i_ = sigm (gv.y + bs1);
        const float c_ = tanhf(gv.z + bs2);
        const float o_ = sigm (gv.w + bs3);
        const float cv = cx[(size_t)row * HID + j];
        const float cy = f_ * cv + i_ * c_;
        const float hy = o_ * tanhf(cy);
        out[(size_t)row * HID + j] = hy;
        out[(size_t)BROWS * HID + (size_t)row * HID + j] = cy;
    }
}

extern "C" void kernel_launch(void* const* d_in, const int* in_sizes, int n_in,
                              void* d_out, int out_size)
{
    const float* x  = (const float*)d_in[0];
    const float* hx = (const float*)d_in[1];
    const float* cx = (const float*)d_in[2];
    const float* Wx = (const float*)d_in[3];
    const float* bx = (const float*)d_in[4];
    const float* Wh = (const float*)d_in[5];
    const float* bh = (const float*)d_in[6];
    float* out = (float*)d_out;

    cudaFuncSetAttribute(lstm_mma_fp16_kernel,
                         cudaFuncAttributeMaxDynamicSharedMemorySize, SMEM_TOTAL);
    const int grid = (BROWS / BM) * NUM_NT;   // 2048
    lstm_mma_fp16_kernel<<<grid, 256, SMEM_TOTAL>>>(x, hx, cx, Wx, bx, Wh, bh, out);
}

// round 6
// speedup vs baseline: 1.3520x; 1.3520x over previous
#include <cuda_runtime.h>
#include <cstdint>
#include <math.h>

// ---------------- problem constants ----------------
#define HID    2048
#define BROWS  4096
#define KHALF  2048           // K extent of each half (x/Wx vs hx/Wh)

constexpr int BM = 128;       // rows per CTA
constexpr int BN = 128;       // C cols per CTA (col = h*4 + g -> 32 hidden cols)
constexpr int BK = 32;        // K per smem tile (4 mma k8 steps)
constexpr int NT = 4096 / BK;        // 128 k-tiles
constexpr int HALF_T = 2048 / BK;    // 64
constexpr int NUM_NT = (4 * HID) / BN;  // 64 n-tiles
constexpr int GROUP_M = 8;

// ---------------- smem layout ----------------
// Tiles: 128 rows x 128B. Within a row, float position q holds k(q) where
// q(k) = (k%4)*8 + k/4  (k-permuted so each lane's fragment family is contiguous).
// 16B granules XOR-swizzled with (row & 7).
constexpr int TILE_BYTES = BM * 128;         // 16 KB
constexpr int SM_A0 = 1024;
constexpr int SM_A1 = SM_A0 + TILE_BYTES;
constexpr int SM_B0 = SM_A1 + TILE_BYTES;
constexpr int SM_B1 = SM_B0 + TILE_BYTES;    // ends at 66560
constexpr int CSTRIDE = 132;                 // epilogue C stride (floats)
constexpr int SM_C = 1024;                   // epilogue reuses tile region
constexpr int SMEM_TOTAL = 1024 + BM * CSTRIDE * 4;  // 68608

__device__ __forceinline__ uint32_t tf32r(float x) {   // round-to-nearest tf32
    uint32_t y;
    asm("cvt.rna.tf32.f32 %0, %1;" : "=r"(y) : "f"(x));
    return y;
}
__device__ __forceinline__ float sigm(float v) { return 1.f / (1.f + __expf(-v)); }

__device__ __forceinline__ void mma_tf32(float& c0, float& c1, float& c2, float& c3,
                                         float a0, float a1, float a2, float a3,
                                         float b0, float b1) {
    asm volatile(
        "mma.sync.aligned.m16n8k8.row.col.f32.tf32.tf32.f32 "
        "{%0,%1,%2,%3}, {%4,%5,%6,%7}, {%8,%9}, {%0,%1,%2,%3};"
        : "+f"(c0), "+f"(c1), "+f"(c2), "+f"(c3)
        : "r"(__float_as_uint(a0)), "r"(__float_as_uint(a1)),
          "r"(__float_as_uint(a2)), "r"(__float_as_uint(a3)),
          "r"(__float_as_uint(b0)), "r"(__float_as_uint(b1)));
}

// ---------------- kernel ----------------
__global__ __launch_bounds__(256, 1)
void lstm_mma_kernel(const float* __restrict__ x,
                     const float* __restrict__ hx,
                     const float* __restrict__ cx,
                     const float* __restrict__ Wx,
                     const float* __restrict__ bx,
                     const float* __restrict__ Wh,
                     const float* __restrict__ bh,
                     float* __restrict__ out)
{
    extern __shared__ __align__(1024) uint8_t smem[];
    const int tid  = threadIdx.x;
    const int wid  = tid >> 5;
    const int lane = tid & 31;
    const int g    = lane >> 2;   // group id (0..7)
    const int tig  = lane & 3;    // thread in group

    // ---- CTA tile mapping (GROUP_M swizzle for L2 reuse of W) ----
    int bid    = blockIdx.x;
    int group  = bid / (GROUP_M * NUM_NT);
    int rem    = bid % (GROUP_M * NUM_NT);
    int m_tile = group * GROUP_M + (rem % GROUP_M);
    int n_tile = rem / GROUP_M;
    const int m0 = m_tile * BM;
    const int j0 = n_tile * (BN / 4);   // 32 hidden cols per CTA

    // ---- per-thread staging descriptors (4 granules per operand per tile) ----
    size_t aoff[4], boff[4];
    int sts_pos[4][4];     // [granule i][float j] byte offset within tile
#pragma unroll
    for (int i = 0; i < 4; i++) {
        int idx = tid + i * 256;
        int row = idx >> 3;          // 0..127 (M row for A, C col for B)
        int kq  = idx & 7;           // 16B source granule along K
        aoff[i] = (size_t)(m0 + row) * KHALF + kq * 4;
        int gg = row & 3, jl = row >> 2;
        boff[i] = ((size_t)(gg * HID + j0 + jl)) * KHALF + kq * 4;
#pragma unroll
        for (int j = 0; j < 4; j++) {
            // float k = 4*kq + j goes to position q = j*8 + kq
            int q  = j * 8 + kq;
            int gr = (q >> 2) ^ (row & 7);
            sts_pos[i][j] = row * 128 + (gr << 4) + ((q & 3) << 2);
        }
    }

    const int smA[2] = {SM_A0, SM_A1};
    const int smB[2] = {SM_B0, SM_B1};

    auto ldg_tile = [&](int t, float4* A, float4* Bv) {
        const float* ap = (t < HALF_T) ? x  : hx;
        const float* wp = (t < HALF_T) ? Wx : Wh;
        const int kofs  = ((t < HALF_T) ? t : (t - HALF_T)) * BK;
#pragma unroll
        for (int i = 0; i < 4; i++) {
            A[i]  = *(const float4*)(ap + aoff[i] + kofs);
            Bv[i] = *(const float4*)(wp + boff[i] + kofs);
        }
    };
    auto sts_tile = [&](int buf, const float4* A, const float4* Bv) {
        uint8_t* a = smem + smA[buf];
        uint8_t* b = smem + smB[buf];
#pragma unroll
        for (int i = 0; i < 4; i++) {
            *(uint32_t*)(a + sts_pos[i][0]) = tf32r(A[i].x);
            *(uint32_t*)(a + sts_pos[i][1]) = tf32r(A[i].y);
            *(uint32_t*)(a + sts_pos[i][2]) = tf32r(A[i].z);
            *(uint32_t*)(a + sts_pos[i][3]) = tf32r(A[i].w);
            *(uint32_t*)(b + sts_pos[i][0]) = tf32r(Bv[i].x);
            *(uint32_t*)(b + sts_pos[i][1]) = tf32r(Bv[i].y);
            *(uint32_t*)(b + sts_pos[i][2]) = tf32r(Bv[i].z);
            *(uint32_t*)(b + sts_pos[i][3]) = tf32r(Bv[i].w);
        }
    };

    // ---- warp tile: 2(M) x 4(N), 64x32 per warp ----
    const int wm = (wid >> 2) * 64;
    const int wn = (wid & 3) * 32;

    // fragment LDS constants: granule (2*tig + half) ^ g, row/col base
    const int cH[2] = { ((2 * tig + 0) ^ g) << 4, ((2 * tig + 1) ^ g) << 4 };

    auto ld_fragsA = [&](int buf, int h, float4* vA) {
        const uint8_t* At = smem + smA[buf];
#pragma unroll
        for (int mi = 0; mi < 4; mi++) {
            vA[2 * mi]     = *(const float4*)(At + (wm + mi * 16 + g)     * 128 + cH[h]);
            vA[2 * mi + 1] = *(const float4*)(At + (wm + mi * 16 + g + 8) * 128 + cH[h]);
        }
    };
    auto ld_fragsB = [&](int buf, int h, float4* vB) {
        const uint8_t* Bt = smem + smB[buf];
#pragma unroll
        for (int ni = 0; ni < 4; ni++)
            vB[ni] = *(const float4*)(Bt + (wn + ni * 8 + g) * 128 + cH[h]);
    };

    float acc[4][4][4];
#pragma unroll
    for (int mi = 0; mi < 4; mi++)
#pragma unroll
        for (int ni = 0; ni < 4; ni++)
#pragma unroll
            for (int q = 0; q < 4; q++) acc[mi][ni][q] = 0.f;

    auto mma_half = [&](const float4* vA, const float4* vB) {
#pragma unroll
        for (int mi = 0; mi < 4; mi++)
#pragma unroll
            for (int ni = 0; ni < 4; ni++) {
                mma_tf32(acc[mi][ni][0], acc[mi][ni][1], acc[mi][ni][2], acc[mi][ni][3],
                         vA[2*mi].x, vA[2*mi+1].x, vA[2*mi].y, vA[2*mi+1].y,
                         vB[ni].x, vB[ni].y);
                mma_tf32(acc[mi][ni][0], acc[mi][ni][1], acc[mi][ni][2], acc[mi][ni][3],
                         vA[2*mi].z, vA[2*mi+1].z, vA[2*mi].w, vA[2*mi+1].w,
                         vB[ni].z, vB[ni].w);
            }
    };

    // ---- prologue ----
    float4 stgA[4], stgB[4];
    ldg_tile(0, stgA, stgB);
    sts_tile(0, stgA, stgB);
    __syncthreads();

    float4 vA0[8], vB0[4], vA1[8], vB1[4];
    ld_fragsA(0, 0, vA0);
    ld_fragsB(0, 0, vB0);

    // ---- mainloop ----
    for (int t = 0; t < NT; t++) {
        const int buf = t & 1;
        if (t + 1 < NT) ldg_tile(t + 1, stgA, stgB);   // global prefetch (dist 1)

        // load half1 fragments while half0 MMAs run
        ld_fragsA(buf, 1, vA1);
        ld_fragsB(buf, 1, vB1);
        mma_half(vA0, vB0);
        mma_half(vA1, vB1);

        if (t + 1 < NT) {
            sts_tile(buf ^ 1, stgA, stgB);
            __syncthreads();
            ld_fragsA(buf ^ 1, 0, vA0);
            ld_fragsB(buf ^ 1, 0, vB0);
        }
    }

    // ---- epilogue: stage C through smem, then fused LSTM math ----
    __syncthreads();   // all warps done reading A/B tiles
    float* Cs = (float*)(smem + SM_C);
#pragma unroll
    for (int mi = 0; mi < 4; mi++) {
#pragma unroll
        for (int ni = 0; ni < 4; ni++) {
            const int r1 = wm + mi * 16 + g;
            const int c0 = wn + ni * 8 + tig * 2;
            *(float2*)(Cs + r1 * CSTRIDE + c0)       = make_float2(acc[mi][ni][0], acc[mi][ni][1]);
            *(float2*)(Cs + (r1 + 8) * CSTRIDE + c0) = make_float2(acc[mi][ni][2], acc[mi][ni][3]);
        }
    }
    __syncthreads();

    // biases for this thread's hidden column (h = lane)
    const int j = j0 + lane;
    const float bs0 = bx[0 * HID + j] + bh[0 * HID + j];
    const float bs1 = bx[1 * HID + j] + bh[1 * HID + j];
    const float bs2 = bx[2 * HID + j] + bh[2 * HID + j];
    const float bs3 = bx[3 * HID + j] + bh[3 * HID + j];

#pragma unroll
    for (int i = 0; i < 16; i++) {
        const int rl  = i * 8 + wid;          // local row 0..127
        const int row = m0 + rl;
        const float4 gv = *(const float4*)(Cs + rl * CSTRIDE + lane * 4);
        const float f_ = sigm (gv.x + bs0);
        const float i_ = sigm (gv.y + bs1);
        const float c_ = tanhf(gv.z + bs2);
        const float o_ = sigm (gv.w + bs3);
        const float cv = cx[(size_t)row * HID + j];
        const float cy = f_ * cv + i_ * c_;
        const float hy = o_ * tanhf(cy);
        out[(size_t)row * HID + j] = hy;
        out[(size_t)BROWS * HID + (size_t)row * HID + j] = cy;
    }
}

extern "C" void kernel_launch(void* const* d_in, const int* in_sizes, int n_in,
                              void* d_out, int out_size)
{
    const float* x  = (const float*)d_in[0];
    const float* hx = (const float*)d_in[1];
    const float* cx = (const float*)d_in[2];
    const float* Wx = (const float*)d_in[3];
    const float* bx = (const float*)d_in[4];
    const float* Wh = (const float*)d_in[5];
    const float* bh = (const float*)d_in[6];
    float* out = (float*)d_out;

    cudaFuncSetAttribute(lstm_mma_kernel,
                         cudaFuncAttributeMaxDynamicSharedMemorySize, SMEM_TOTAL);
    const int grid = (BROWS / BM) * NUM_NT;   // 2048
    lstm_mma_kernel<<<grid, 256, SMEM_TOTAL>>>(x, hx, cx, Wx, bx, Wh, bh, out);
}

// round 7
// speedup vs baseline: 1.5482x; 1.1451x over previous
#include <cuda_runtime.h>
#include <cstdint>
#include <math.h>

// ---------------- problem constants ----------------
#define HID    2048
#define BROWS  4096
#define KHALF  2048           // K extent of each half (x/Wx vs hx/Wh)

constexpr int BM = 128;       // rows per CTA
constexpr int BN = 128;       // C cols per CTA (col = h*4 + g -> 32 hidden cols)
constexpr int BK = 32;        // K per smem tile (4 mma k8 steps)
constexpr int NT = 4096 / BK;        // 128 k-tiles
constexpr int HALF_T = 2048 / BK;    // 64
constexpr int NUM_NT = (4 * HID) / BN;  // 64 n-tiles
constexpr int GROUP_M = 8;
constexpr int NTHREADS = 512;        // 16 warps

// ---------------- smem layout ----------------
// Tiles: 128 rows x 128B. Float position q holds k(q) with q(k) = (k%4)*8 + k/4
// (k-permuted so each lane's fragment family is one float4). 16B granules
// XOR-swizzled with (row & 7).
constexpr int TILE_BYTES = BM * 128;         // 16 KB
constexpr int SM_A0 = 1024;
constexpr int SM_A1 = SM_A0 + TILE_BYTES;
constexpr int SM_B0 = SM_A1 + TILE_BYTES;
constexpr int SM_B1 = SM_B0 + TILE_BYTES;    // ends at 66560
constexpr int CSTRIDE = 132;                 // epilogue C stride (floats)
constexpr int SM_C = 1024;                   // epilogue reuses tile region
constexpr int SMEM_TOTAL = 1024 + BM * CSTRIDE * 4;  // 68608

__device__ __forceinline__ uint32_t tf32r(float x) {   // round-to-nearest tf32
    uint32_t y;
    asm("cvt.rna.tf32.f32 %0, %1;" : "=r"(y) : "f"(x));
    return y;
}
__device__ __forceinline__ float sigm(float v) { return 1.f / (1.f + __expf(-v)); }

__device__ __forceinline__ void mma_tf32(float& c0, float& c1, float& c2, float& c3,
                                         float a0, float a1, float a2, float a3,
                                         float b0, float b1) {
    asm volatile(
        "mma.sync.aligned.m16n8k8.row.col.f32.tf32.tf32.f32 "
        "{%0,%1,%2,%3}, {%4,%5,%6,%7}, {%8,%9}, {%0,%1,%2,%3};"
        : "+f"(c0), "+f"(c1), "+f"(c2), "+f"(c3)
        : "r"(__float_as_uint(a0)), "r"(__float_as_uint(a1)),
          "r"(__float_as_uint(a2)), "r"(__float_as_uint(a3)),
          "r"(__float_as_uint(b0)), "r"(__float_as_uint(b1)));
}

// ---------------- kernel ----------------
__global__ __launch_bounds__(NTHREADS, 1)
void lstm_mma_kernel(const float* __restrict__ x,
                     const float* __restrict__ hx,
                     const float* __restrict__ cx,
                     const float* __restrict__ Wx,
                     const float* __restrict__ bx,
                     const float* __restrict__ Wh,
                     const float* __restrict__ bh,
                     float* __restrict__ out)
{
    extern __shared__ __align__(1024) uint8_t smem[];
    const int tid  = threadIdx.x;
    const int wid  = tid >> 5;    // 0..15
    const int lane = tid & 31;
    const int g    = lane >> 2;   // group id (0..7)
    const int tig  = lane & 3;    // thread in group

    // ---- CTA tile mapping (GROUP_M swizzle for L2 reuse of W) ----
    int bid    = blockIdx.x;
    int group  = bid / (GROUP_M * NUM_NT);
    int rem    = bid % (GROUP_M * NUM_NT);
    int m_tile = group * GROUP_M + (rem % GROUP_M);
    int n_tile = rem / GROUP_M;
    const int m0 = m_tile * BM;
    const int j0 = n_tile * (BN / 4);   // 32 hidden cols per CTA

    // ---- per-thread staging descriptors (2 granules per operand per tile) ----
    size_t aoff[2], boff[2];
    int sts_pos[2][4];     // [granule i][float j] byte offset within tile
#pragma unroll
    for (int i = 0; i < 2; i++) {
        int idx = tid + i * NTHREADS;   // 0..1023
        int row = idx >> 3;             // 0..127 (M row for A, C col for B)
        int kq  = idx & 7;              // 16B source granule along K
        aoff[i] = (size_t)(m0 + row) * KHALF + kq * 4;
        int gg = row & 3, jl = row >> 2;
        boff[i] = ((size_t)(gg * HID + j0 + jl)) * KHALF + kq * 4;
#pragma unroll
        for (int j = 0; j < 4; j++) {
            // float k = 4*kq + j goes to position q = j*8 + kq
            int q  = j * 8 + kq;
            int gr = (q >> 2) ^ (row & 7);
            sts_pos[i][j] = row * 128 + (gr << 4) + ((q & 3) << 2);
        }
    }

    const int smA[2] = {SM_A0, SM_A1};
    const int smB[2] = {SM_B0, SM_B1};

    auto ldg_tile = [&](int t, float4* A, float4* Bv) {
        const float* ap = (t < HALF_T) ? x  : hx;
        const float* wp = (t < HALF_T) ? Wx : Wh;
        const int kofs  = ((t < HALF_T) ? t : (t - HALF_T)) * BK;
#pragma unroll
        for (int i = 0; i < 2; i++) {
            A[i]  = *(const float4*)(ap + aoff[i] + kofs);
            Bv[i] = *(const float4*)(wp + boff[i] + kofs);
        }
    };
    auto sts_tile = [&](int buf, const float4* A, const float4* Bv) {
        uint8_t* a = smem + smA[buf];
        uint8_t* b = smem + smB[buf];
#pragma unroll
        for (int i = 0; i < 2; i++) {
            *(uint32_t*)(a + sts_pos[i][0]) = tf32r(A[i].x);
            *(uint32_t*)(a + sts_pos[i][1]) = tf32r(A[i].y);
            *(uint32_t*)(a + sts_pos[i][2]) = tf32r(A[i].z);
            *(uint32_t*)(a + sts_pos[i][3]) = tf32r(A[i].w);
            *(uint32_t*)(b + sts_pos[i][0]) = tf32r(Bv[i].x);
            *(uint32_t*)(b + sts_pos[i][1]) = tf32r(Bv[i].y);
            *(uint32_t*)(b + sts_pos[i][2]) = tf32r(Bv[i].z);
            *(uint32_t*)(b + sts_pos[i][3]) = tf32r(Bv[i].w);
        }
    };

    // ---- warp tile: 4(M) x 4(N) warp grid, 32x32 per warp ----
    const int wm = (wid >> 2) * 32;
    const int wn = (wid & 3) * 32;

    // fragment LDS: granule (2*tig + half) ^ g  (row&7 == g for all frag rows)
    const int cH[2] = { ((2 * tig + 0) ^ g) << 4, ((2 * tig + 1) ^ g) << 4 };

    float acc[2][4][4];
#pragma unroll
    for (int mi = 0; mi < 2; mi++)
#pragma unroll
        for (int ni = 0; ni < 4; ni++)
#pragma unroll
            for (int q = 0; q < 4; q++) acc[mi][ni][q] = 0.f;

    // ---- prologue ----
    float4 stgA[2], stgB[2];
    ldg_tile(0, stgA, stgB);
    sts_tile(0, stgA, stgB);
    __syncthreads();

    // ---- mainloop ----
    for (int t = 0; t < NT; t++) {
        const int buf = t & 1;
        if (t + 1 < NT) ldg_tile(t + 1, stgA, stgB);   // global prefetch (dist 1)

        const uint8_t* At = smem + smA[buf];
        const uint8_t* Bt = smem + smB[buf];

#pragma unroll
        for (int h = 0; h < 2; h++) {
            float4 vA[4], vB[4];
#pragma unroll
            for (int mi = 0; mi < 2; mi++) {
                vA[2 * mi]     = *(const float4*)(At + (wm + mi * 16 + g)     * 128 + cH[h]);
                vA[2 * mi + 1] = *(const float4*)(At + (wm + mi * 16 + g + 8) * 128 + cH[h]);
            }
#pragma unroll
            for (int ni = 0; ni < 4; ni++)
                vB[ni] = *(const float4*)(Bt + (wn + ni * 8 + g) * 128 + cH[h]);
#pragma unroll
            for (int mi = 0; mi < 2; mi++)
#pragma unroll
                for (int ni = 0; ni < 4; ni++) {
                    mma_tf32(acc[mi][ni][0], acc[mi][ni][1], acc[mi][ni][2], acc[mi][ni][3],
                             vA[2*mi].x, vA[2*mi+1].x, vA[2*mi].y, vA[2*mi+1].y,
                             vB[ni].x, vB[ni].y);
                    mma_tf32(acc[mi][ni][0], acc[mi][ni][1], acc[mi][ni][2], acc[mi][ni][3],
                             vA[2*mi].z, vA[2*mi+1].z, vA[2*mi].w, vA[2*mi+1].w,
                             vB[ni].z, vB[ni].w);
                }
        }

        if (t + 1 < NT) {
            sts_tile(buf ^ 1, stgA, stgB);
            __syncthreads();
        }
    }

    // ---- epilogue: stage C through smem, then fused LSTM math ----
    __syncthreads();   // all warps done reading A/B tiles
    float* Cs = (float*)(smem + SM_C);
#pragma unroll
    for (int mi = 0; mi < 2; mi++) {
#pragma unroll
        for (int ni = 0; ni < 4; ni++) {
            const int r1 = wm + mi * 16 + g;
            const int c0 = wn + ni * 8 + tig * 2;
            *(float2*)(Cs + r1 * CSTRIDE + c0)       = make_float2(acc[mi][ni][0], acc[mi][ni][1]);
            *(float2*)(Cs + (r1 + 8) * CSTRIDE + c0) = make_float2(acc[mi][ni][2], acc[mi][ni][3]);
        }
    }
    __syncthreads();

    // biases for this thread's hidden column (h = lane)
    const int j = j0 + lane;
    const float bs0 = bx[0 * HID + j] + bh[0 * HID + j];
    const float bs1 = bx[1 * HID + j] + bh[1 * HID + j];
    const float bs2 = bx[2 * HID + j] + bh[2 * HID + j];
    const float bs3 = bx[3 * HID + j] + bh[3 * HID + j];

#pragma unroll
    for (int i = 0; i < 8; i++) {
        const int rl  = i * 16 + wid;         // local row 0..127
        const int row = m0 + rl;
        const float4 gv = *(const float4*)(Cs + rl * CSTRIDE + lane * 4);
        const float f_ = sigm (gv.x + bs0);
        const float i_ = sigm (gv.y + bs1);
        const float c_ = tanhf(gv.z + bs2);
        const float o_ = sigm (gv.w + bs3);
        const float cv = cx[(size_t)row * HID + j];
        const float cy = f_ * cv + i_ * c_;
        const float hy = o_ * tanhf(cy);
        out[(size_t)row * HID + j] = hy;
        out[(size_t)BROWS * HID + (size_t)row * HID + j] = cy;
    }
}

extern "C" void kernel_launch(void* const* d_in, const int* in_sizes, int n_in,
                              void* d_out, int out_size)
{
    const float* x  = (const float*)d_in[0];
    const float* hx = (const float*)d_in[1];
    const float* cx = (const float*)d_in[2];
    const float* Wx = (const float*)d_in[3];
    const float* bx = (const float*)d_in[4];
    const float* Wh = (const float*)d_in[5];
    const float* bh = (const float*)d_in[6];
    float* out = (float*)d_out;

    cudaFuncSetAttribute(lstm_mma_kernel,
                         cudaFuncAttributeMaxDynamicSharedMemorySize, SMEM_TOTAL);
    const int grid = (BROWS / BM) * NUM_NT;   // 2048
    lstm_mma_kernel<<<grid, NTHREADS, SMEM_TOTAL>>>(x, hx, cx, Wx, bx, Wh, bh, out);
}

// round 8
// speedup vs baseline: 1.8406x; 1.1889x over previous
#include <cuda_runtime.h>
#include <cuda_fp16.h>
#include <cstdint>
#include <math.h>

// ---------------- problem constants ----------------
#define HID    2048
#define BROWS  4096
#define KHALF  2048           // K extent of each half (x/Wx vs hx/Wh)

constexpr int BM = 128;       // rows per CTA
constexpr int BN = 128;       // C cols per CTA (col = h*4 + g -> 32 hidden cols)
constexpr int BK = 32;        // K per smem tile (2 mma k16 steps)
constexpr int NT = 4096 / BK;        // 128 k-tiles
constexpr int HALF_T = 2048 / BK;    // 64
constexpr int NUM_NT = (4 * HID) / BN;  // 64 n-tiles
constexpr int GROUP_M = 8;
constexpr int NTHREADS = 512;        // 16 warps

// ---------------- smem layout ----------------
// fp16 tiles: 128 rows x 32 fp16 = 64B/row (4 x 16B granules).
// k-permutation within a row: k -> pos p = t*8 + h*4 + s*2 + d, where
//   d=k&1, t=(k>>1)&3, s=(k>>3)&1, h=(k>>4)&1
// so lane tig's whole-BK fragment family {k: (k>>1)&3==tig} is ONE 16B granule,
// ordered as u32 words (h,s) = (0,0),(0,1),(1,0),(1,1).
// Granule swizzle: granule ^= (row>>1)&1  (conflict-free for STS.32 pattern and
// for LDS.128 fragment phases; all fragment rows share the same swizzle bit).
constexpr int TILE_B = BM * 64;              // 8 KB per fp16 tile
constexpr int SM_A0 = 1024;
constexpr int SM_A1 = SM_A0 + TILE_B;
constexpr int SM_B0 = SM_A1 + TILE_B;
constexpr int SM_B1 = SM_B0 + TILE_B;        // ends at 33792
constexpr int CSTRIDE = 132;                 // epilogue C stride (floats)
constexpr int SM_C = 1024;                   // epilogue reuses tile region
constexpr int SMEM_TOTAL = 1024 + BM * CSTRIDE * 4;  // 68608

__device__ __forceinline__ float sigm(float v) { return 1.f / (1.f + __expf(-v)); }
__device__ __forceinline__ uint32_t h2u(__half2 h) { return *(uint32_t*)&h; }

__device__ __forceinline__ void mma_f16(float& c0, float& c1, float& c2, float& c3,
                                        uint32_t a0, uint32_t a1, uint32_t a2, uint32_t a3,
                                        uint32_t b0, uint32_t b1) {
    asm volatile(
        "mma.sync.aligned.m16n8k16.row.col.f32.f16.f16.f32 "
        "{%0,%1,%2,%3}, {%4,%5,%6,%7}, {%8,%9}, {%0,%1,%2,%3};"
        : "+f"(c0), "+f"(c1), "+f"(c2), "+f"(c3)
        : "r"(a0), "r"(a1), "r"(a2), "r"(a3), "r"(b0), "r"(b1));
}

// ---------------- kernel ----------------
__global__ __launch_bounds__(NTHREADS, 1)
void lstm_mma_kernel(const float* __restrict__ x,
                     const float* __restrict__ hx,
                     const float* __restrict__ cx,
                     const float* __restrict__ Wx,
                     const float* __restrict__ bx,
                     const float* __restrict__ Wh,
                     const float* __restrict__ bh,
                     float* __restrict__ out)
{
    extern __shared__ __align__(1024) uint8_t smem[];
    const int tid  = threadIdx.x;
    const int wid  = tid >> 5;    // 0..15
    const int lane = tid & 31;
    const int g    = lane >> 2;   // group id (0..7)
    const int tig  = lane & 3;    // thread in group

    // ---- CTA tile mapping (GROUP_M swizzle for L2 reuse of W) ----
    int bid    = blockIdx.x;
    int group  = bid / (GROUP_M * NUM_NT);
    int rem    = bid % (GROUP_M * NUM_NT);
    int m_tile = group * GROUP_M + (rem % GROUP_M);
    int n_tile = rem / GROUP_M;
    const int m0 = m_tile * BM;
    const int j0 = n_tile * (BN / 4);   // 32 hidden cols per CTA

    // ---- per-thread staging descriptors (2 granules per operand per tile) ----
    // source granule: row = idx>>3, kq = idx&7 (4 fp32 at k = 4*kq .. 4*kq+3)
    // dest: two half2 words m = 2*kq (floats 0,1) and m+1 (floats 2,3):
    //   word w(m) = (m&3)*4 + ((m>>3)&1)*2 + ((m>>2)&1), granule-swizzled.
    size_t aoff[2], boff[2];
    int sts_b0[2], sts_b1[2];   // byte offsets in tile for the two half2 words
#pragma unroll
    for (int i = 0; i < 2; i++) {
        int idx = tid + i * NTHREADS;   // 0..1023
        int row = idx >> 3;             // 0..127
        int kq  = idx & 7;
        aoff[i] = (size_t)(m0 + row) * KHALF + kq * 4;
        int gg = row & 3, jl = row >> 2;
        boff[i] = ((size_t)(gg * HID + j0 + jl)) * KHALF + kq * 4;
        int sw = (row >> 1) & 1;        // granule swizzle bit
        int m1 = 2 * kq, m2 = 2 * kq + 1;
        int w1 = (m1 & 3) * 4 + ((m1 >> 3) & 1) * 2 + ((m1 >> 2) & 1);
        int w2 = (m2 & 3) * 4 + ((m2 >> 3) & 1) * 2 + ((m2 >> 2) & 1);
        sts_b0[i] = row * 64 + ((((w1 >> 2) ^ sw) << 2) + (w1 & 3)) * 4;
        sts_b1[i] = row * 64 + ((((w2 >> 2) ^ sw) << 2) + (w2 & 3)) * 4;
    }

    const int smA[2] = {SM_A0, SM_A1};
    const int smB[2] = {SM_B0, SM_B1};

    auto ldg_tile = [&](int t, float4* A, float4* Bv) {
        const float* ap = (t < HALF_T) ? x  : hx;
        const float* wp = (t < HALF_T) ? Wx : Wh;
        const int kofs  = ((t < HALF_T) ? t : (t - HALF_T)) * BK;
#pragma unroll
        for (int i = 0; i < 2; i++) {
            A[i]  = *(const float4*)(ap + aoff[i] + kofs);
            Bv[i] = *(const float4*)(wp + boff[i] + kofs);
        }
    };
    auto sts_tile = [&](int buf, const float4* A, const float4* Bv) {
        uint8_t* a = smem + smA[buf];
        uint8_t* b = smem + smB[buf];
#pragma unroll
        for (int i = 0; i < 2; i++) {
            *(uint32_t*)(a + sts_b0[i]) = h2u(__floats2half2_rn(A[i].x,  A[i].y));
            *(uint32_t*)(a + sts_b1[i]) = h2u(__floats2half2_rn(A[i].z,  A[i].w));
            *(uint32_t*)(b + sts_b0[i]) = h2u(__floats2half2_rn(Bv[i].x, Bv[i].y));
            *(uint32_t*)(b + sts_b1[i]) = h2u(__floats2half2_rn(Bv[i].z, Bv[i].w));
        }
    };

    // ---- warp tile: 4(M) x 4(N) warp grid, 32x32 per warp ----
    const int wm = (wid >> 2) * 32;
    const int wn = (wid & 3) * 32;

    // fragment granule byte offset: for all fragment rows, (row>>1)&1 == (g>>1)&1
    const int cgo = (tig ^ ((g >> 1) & 1)) << 4;

    float acc[2][4][4];
#pragma unroll
    for (int mi = 0; mi < 2; mi++)
#pragma unroll
        for (int ni = 0; ni < 4; ni++)
#pragma unroll
            for (int q = 0; q < 4; q++) acc[mi][ni][q] = 0.f;

    // ---- prologue ----
    float4 stgA[2], stgB[2];
    ldg_tile(0, stgA, stgB);
    sts_tile(0, stgA, stgB);
    __syncthreads();

    // ---- mainloop ----
    for (int t = 0; t < NT; t++) {
        const int buf = t & 1;
        if (t + 1 < NT) ldg_tile(t + 1, stgA, stgB);   // global prefetch (dist 1)

        const uint8_t* At = smem + smA[buf];
        const uint8_t* Bt = smem + smB[buf];

        uint4 vA[4], vB[4];
#pragma unroll
        for (int mi = 0; mi < 2; mi++) {
            vA[2 * mi]     = *(const uint4*)(At + (wm + mi * 16 + g)     * 64 + cgo);
            vA[2 * mi + 1] = *(const uint4*)(At + (wm + mi * 16 + g + 8) * 64 + cgo);
        }
#pragma unroll
        for (int ni = 0; ni < 4; ni++)
            vB[ni] = *(const uint4*)(Bt + (wn + ni * 8 + g) * 64 + cgo);

        // h = 0 (k 0..15): words (.x=.s0 lo-k, .y hi-k); h = 1 (k 16..31): (.z,.w)
#pragma unroll
        for (int mi = 0; mi < 2; mi++)
#pragma unroll
            for (int ni = 0; ni < 4; ni++) {
                mma_f16(acc[mi][ni][0], acc[mi][ni][1], acc[mi][ni][2], acc[mi][ni][3],
                        vA[2*mi].x, vA[2*mi+1].x, vA[2*mi].y, vA[2*mi+1].y,
                        vB[ni].x, vB[ni].y);
                mma_f16(acc[mi][ni][0], acc[mi][ni][1], acc[mi][ni][2], acc[mi][ni][3],
                        vA[2*mi].z, vA[2*mi+1].z, vA[2*mi].w, vA[2*mi+1].w,
                        vB[ni].z, vB[ni].w);
            }

        if (t + 1 < NT) {
            sts_tile(buf ^ 1, stgA, stgB);
            __syncthreads();
        }
    }

    // ---- epilogue: stage C through smem, then fused LSTM math ----
    __syncthreads();   // all warps done reading A/B tiles
    float* Cs = (float*)(smem + SM_C);
#pragma unroll
    for (int mi = 0; mi < 2; mi++) {
#pragma unroll
        for (int ni = 0; ni < 4; ni++) {
            const int r1 = wm + mi * 16 + g;
            const int c0 = wn + ni * 8 + tig * 2;
            *(float2*)(Cs + r1 * CSTRIDE + c0)       = make_float2(acc[mi][ni][0], acc[mi][ni][1]);
            *(float2*)(Cs + (r1 + 8) * CSTRIDE + c0) = make_float2(acc[mi][ni][2], acc[mi][ni][3]);
        }
    }
    __syncthreads();

    // biases for this thread's hidden column (h = lane)
    const int j = j0 + lane;
    const float bs0 = bx[0 * HID + j] + bh[0 * HID + j];
    const float bs1 = bx[1 * HID + j] + bh[1 * HID + j];
    const float bs2 = bx[2 * HID + j] + bh[2 * HID + j];
    const float bs3 = bx[3 * HID + j] + bh[3 * HID + j];

#pragma unroll
    for (int i = 0; i < 8; i++) {
        const int rl  = i * 16 + wid;         // local row 0..127
        const int row = m0 + rl;
        const float4 gv = *(const float4*)(Cs + rl * CSTRIDE + lane * 4);
        const float f_ = sigm (gv.x + bs0);
        const float i_ = sigm (gv.y + bs1);
        const float c_ = tanhf(gv.z + bs2);
        const float o_ = sigm (gv.w + bs3);
        const float cv = cx[(size_t)row * HID + j];
        const float cy = f_ * cv + i_ * c_;
        const float hy = o_ * tanhf(cy);
        out[(size_t)row * HID + j] = hy;
        out[(size_t)BROWS * HID + (size_t)row * HID + j] = cy;
    }
}

extern "C" void kernel_launch(void* const* d_in, const int* in_sizes, int n_in,
                              void* d_out, int out_size)
{
    const float* x  = (const float*)d_in[0];
    const float* hx = (const float*)d_in[1];
    const float* cx = (const float*)d_in[2];
    const float* Wx = (const float*)d_in[3];
    const float* bx = (const float*)d_in[4];
    const float* Wh = (const float*)d_in[5];
    const float* bh = (const float*)d_in[6];
    float* out = (float*)d_out;

    cudaFuncSetAttribute(lstm_mma_kernel,
                         cudaFuncAttributeMaxDynamicSharedMemorySize, SMEM_TOTAL);
    const int grid = (BROWS / BM) * NUM_NT;   // 2048
    lstm_mma_kernel<<<grid, NTHREADS, SMEM_TOTAL>>>(x, hx, cx, Wx, bx, Wh, bh, out);
}

// round 9
// speedup vs baseline: 2.3987x; 1.3032x over previous
#include <cuda_runtime.h>
#include <cuda_fp16.h>
#include <cstdint>
#include <math.h>

// ---------------- problem constants ----------------
#define HID    2048
#define BROWS  4096
#define KHALF  2048           // K extent of each half (x/Wx vs hx/Wh)

constexpr int BM = 128;       // rows per CTA
constexpr int BN = 128;       // C cols per CTA (col = h*4 + g -> 32 hidden cols)
constexpr int BK = 32;        // K per smem tile (2 mma k16 steps)
constexpr int NT = 4096 / BK;        // 128 k-tiles
constexpr int HALF_T = 2048 / BK;    // 64
constexpr int NUM_NT = (4 * HID) / BN;  // 64 n-tiles
constexpr int GROUP_M = 8;
constexpr int NTHREADS = 512;        // 16 warps

// ---------------- smem layout ----------------
// fp16 tiles: 128 rows x 32 fp16 = 64B/row (4 x 16B granules), k-permuted so
// lane tig's whole-BK fragment family is ONE 16B granule (see R8 derivation).
// Granule swizzle: granule ^= (row>>1)&1.
// FOUR buffers per operand; tile t -> buffer t&3; barrier every 2 tiles.
constexpr int TILE_B = BM * 64;              // 8 KB per fp16 tile
constexpr int SM_A0 = 1024;                  // A buffers: SM_A0 + b*TILE_B
constexpr int SM_B0 = SM_A0 + 4 * TILE_B;    // B buffers: SM_B0 + b*TILE_B
constexpr int CSTRIDE = 132;                 // epilogue C stride (floats)
constexpr int SM_C = 1024;                   // epilogue reuses tile region
constexpr int SMEM_TOTAL = 1024 + BM * CSTRIDE * 4;  // 68608 (> 1024+64K mainloop)

__device__ __forceinline__ float sigm(float v) { return 1.f / (1.f + __expf(-v)); }
__device__ __forceinline__ uint32_t h2u(__half2 h) { return *(uint32_t*)&h; }

__device__ __forceinline__ void mma_f16(float& c0, float& c1, float& c2, float& c3,
                                        uint32_t a0, uint32_t a1, uint32_t a2, uint32_t a3,
                                        uint32_t b0, uint32_t b1) {
    asm volatile(
        "mma.sync.aligned.m16n8k16.row.col.f32.f16.f16.f32 "
        "{%0,%1,%2,%3}, {%4,%5,%6,%7}, {%8,%9}, {%0,%1,%2,%3};"
        : "+f"(c0), "+f"(c1), "+f"(c2), "+f"(c3)
        : "r"(a0), "r"(a1), "r"(a2), "r"(a3), "r"(b0), "r"(b1));
}

// ---------------- kernel ----------------
__global__ __launch_bounds__(NTHREADS, 1)
void lstm_mma_kernel(const float* __restrict__ x,
                     const float* __restrict__ hx,
                     const float* __restrict__ cx,
                     const float* __restrict__ Wx,
                     const float* __restrict__ bx,
                     const float* __restrict__ Wh,
                     const float* __restrict__ bh,
                     float* __restrict__ out)
{
    extern __shared__ __align__(1024) uint8_t smem[];
    const int tid  = threadIdx.x;
    const int wid  = tid >> 5;    // 0..15
    const int lane = tid & 31;
    const int g    = lane >> 2;   // group id (0..7)
    const int tig  = lane & 3;    // thread in group

    // ---- CTA tile mapping (GROUP_M swizzle for L2 reuse of W) ----
    int bid    = blockIdx.x;
    int group  = bid / (GROUP_M * NUM_NT);
    int rem    = bid % (GROUP_M * NUM_NT);
    int m_tile = group * GROUP_M + (rem % GROUP_M);
    int n_tile = rem / GROUP_M;
    const int m0 = m_tile * BM;
    const int j0 = n_tile * (BN / 4);   // 32 hidden cols per CTA

    // ---- per-thread staging descriptors (2 granules per operand per tile) ----
    size_t aoff[2], boff[2];
    int sts_b0[2], sts_b1[2];
#pragma unroll
    for (int i = 0; i < 2; i++) {
        int idx = tid + i * NTHREADS;   // 0..1023
        int row = idx >> 3;             // 0..127
        int kq  = idx & 7;
        aoff[i] = (size_t)(m0 + row) * KHALF + kq * 4;
        int gg = row & 3, jl = row >> 2;
        boff[i] = ((size_t)(gg * HID + j0 + jl)) * KHALF + kq * 4;
        int sw = (row >> 1) & 1;        // granule swizzle bit
        int m1 = 2 * kq, m2 = 2 * kq + 1;
        int w1 = (m1 & 3) * 4 + ((m1 >> 3) & 1) * 2 + ((m1 >> 2) & 1);
        int w2 = (m2 & 3) * 4 + ((m2 >> 3) & 1) * 2 + ((m2 >> 2) & 1);
        sts_b0[i] = row * 64 + ((((w1 >> 2) ^ sw) << 2) + (w1 & 3)) * 4;
        sts_b1[i] = row * 64 + ((((w2 >> 2) ^ sw) << 2) + (w2 & 3)) * 4;
    }

    auto ldg_tile = [&](int t, float4* A, float4* Bv) {
        const float* ap = (t < HALF_T) ? x  : hx;
        const float* wp = (t < HALF_T) ? Wx : Wh;
        const int kofs  = ((t < HALF_T) ? t : (t - HALF_T)) * BK;
#pragma unroll
        for (int i = 0; i < 2; i++) {
            A[i]  = *(const float4*)(ap + aoff[i] + kofs);
            Bv[i] = *(const float4*)(wp + boff[i] + kofs);
        }
    };
    auto sts_tile = [&](int t, const float4* A, const float4* Bv) {
        uint8_t* a = smem + SM_A0 + (t & 3) * TILE_B;
        uint8_t* b = smem + SM_B0 + (t & 3) * TILE_B;
#pragma unroll
        for (int i = 0; i < 2; i++) {
            *(uint32_t*)(a + sts_b0[i]) = h2u(__floats2half2_rn(A[i].x,  A[i].y));
            *(uint32_t*)(a + sts_b1[i]) = h2u(__floats2half2_rn(A[i].z,  A[i].w));
            *(uint32_t*)(b + sts_b0[i]) = h2u(__floats2half2_rn(Bv[i].x, Bv[i].y));
            *(uint32_t*)(b + sts_b1[i]) = h2u(__floats2half2_rn(Bv[i].z, Bv[i].w));
        }
    };

    // ---- warp tile: 4(M) x 4(N) warp grid, 32x32 per warp ----
    const int wm = (wid >> 2) * 32;
    const int wn = (wid & 3) * 32;
    const int cgo = (tig ^ ((g >> 1) & 1)) << 4;   // fragment granule offset

    float acc[2][4][4];
#pragma unroll
    for (int mi = 0; mi < 2; mi++)
#pragma unroll
        for (int ni = 0; ni < 4; ni++)
#pragma unroll
            for (int q = 0; q < 4; q++) acc[mi][ni][q] = 0.f;

    auto mma_tile = [&](int t) {
        const uint8_t* At = smem + SM_A0 + (t & 3) * TILE_B;
        const uint8_t* Bt = smem + SM_B0 + (t & 3) * TILE_B;
        uint4 vA[4], vB[4];
#pragma unroll
        for (int mi = 0; mi < 2; mi++) {
            vA[2 * mi]     = *(const uint4*)(At + (wm + mi * 16 + g)     * 64 + cgo);
            vA[2 * mi + 1] = *(const uint4*)(At + (wm + mi * 16 + g + 8) * 64 + cgo);
        }
#pragma unroll
        for (int ni = 0; ni < 4; ni++)
            vB[ni] = *(const uint4*)(Bt + (wn + ni * 8 + g) * 64 + cgo);
#pragma unroll
        for (int mi = 0; mi < 2; mi++)
#pragma unroll
            for (int ni = 0; ni < 4; ni++) {
                mma_f16(acc[mi][ni][0], acc[mi][ni][1], acc[mi][ni][2], acc[mi][ni][3],
                        vA[2*mi].x, vA[2*mi+1].x, vA[2*mi].y, vA[2*mi+1].y,
                        vB[ni].x, vB[ni].y);
                mma_f16(acc[mi][ni][0], acc[mi][ni][1], acc[mi][ni][2], acc[mi][ni][3],
                        vA[2*mi].z, vA[2*mi+1].z, vA[2*mi].w, vA[2*mi+1].w,
                        vB[ni].z, vB[ni].w);
            }
    };

    // ---- prologue: tiles 0,1 -> smem; tiles 2,3 -> staging regs ----
    float4 sA0[2], sB0[2], sA1[2], sB1[2];
    ldg_tile(0, sA0, sB0);
    ldg_tile(1, sA1, sB1);
    sts_tile(0, sA0, sB0);
    sts_tile(1, sA1, sB1);
    ldg_tile(2, sA0, sB0);
    ldg_tile(3, sA1, sB1);
    __syncthreads();

    // ---- mainloop: 2 tiles per iteration, one barrier per pair ----
#pragma unroll 1
    for (int p = 0; p < NT / 2; p++) {
        const int t0 = 2 * p;
        mma_tile(t0);
        if (p + 1 < NT / 2) {
            sts_tile(t0 + 2, sA0, sB0);              // staged LDG from pair p-1
            if (t0 + 4 < NT) ldg_tile(t0 + 4, sA0, sB0);
        }
        mma_tile(t0 + 1);
        if (p + 1 < NT / 2) {
            sts_tile(t0 + 3, sA1, sB1);
            if (t0 + 5 < NT) ldg_tile(t0 + 5, sA1, sB1);
            __syncthreads();
        }
    }

    // ---- epilogue: stage C through smem, then fused LSTM math ----
    __syncthreads();   // all warps done reading tiles
    float* Cs = (float*)(smem + SM_C);
#pragma unroll
    for (int mi = 0; mi < 2; mi++) {
#pragma unroll
        for (int ni = 0; ni < 4; ni++) {
            const int r1 = wm + mi * 16 + g;
            const int c0 = wn + ni * 8 + tig * 2;
            *(float2*)(Cs + r1 * CSTRIDE + c0)       = make_float2(acc[mi][ni][0], acc[mi][ni][1]);
            *(float2*)(Cs + (r1 + 8) * CSTRIDE + c0) = make_float2(acc[mi][ni][2], acc[mi][ni][3]);
        }
    }
    __syncthreads();

    // biases for this thread's hidden column (h = lane)
    const int j = j0 + lane;
    const float bs0 = bx[0 * HID + j] + bh[0 * HID + j];
    const float bs1 = bx[1 * HID + j] + bh[1 * HID + j];
    const float bs2 = bx[2 * HID + j] + bh[2 * HID + j];
    const float bs3 = bx[3 * HID + j] + bh[3 * HID + j];

#pragma unroll
    for (int i = 0; i < 8; i++) {
        const int rl  = i * 16 + wid;         // local row 0..127
        const int row = m0 + rl;
        const float4 gv = *(const float4*)(Cs + rl * CSTRIDE + lane * 4);
        const float f_ = sigm (gv.x + bs0);
        const float i_ = sigm (gv.y + bs1);
        const float c_ = tanhf(gv.z + bs2);
        const float o_ = sigm (gv.w + bs3);
        const float cv = cx[(size_t)row * HID + j];
        const float cy = f_ * cv + i_ * c_;
        const float hy = o_ * tanhf(cy);
        out[(size_t)row * HID + j] = hy;
        out[(size_t)BROWS * HID + (size_t)row * HID + j] = cy;
    }
}

extern "C" void kernel_launch(void* const* d_in, const int* in_sizes, int n_in,
                              void* d_out, int out_size)
{
    const float* x  = (const float*)d_in[0];
    const float* hx = (const float*)d_in[1];
    const float* cx = (const float*)d_in[2];
    const float* Wx = (const float*)d_in[3];
    const float* bx = (const float*)d_in[4];
    const float* Wh = (const float*)d_in[5];
    const float* bh = (const float*)d_in[6];
    float* out = (float*)d_out;

    cudaFuncSetAttribute(lstm_mma_kernel,
                         cudaFuncAttributeMaxDynamicSharedMemorySize, SMEM_TOTAL);
    const int grid = (BROWS / BM) * NUM_NT;   // 2048
    lstm_mma_kernel<<<grid, NTHREADS, SMEM_TOTAL>>>(x, hx, cx, Wx, bx, Wh, bh, out);
}

// round 10
// speedup vs baseline: 3.1940x; 1.3316x over previous
#include <cuda_runtime.h>
#include <cuda_fp16.h>
#include <cstdint>
#include <math.h>

// ---------------- problem constants ----------------
#define HID    2048
#define BROWS  4096
#define KHALF  2048

constexpr int BM = 128;
constexpr int BN = 128;              // C cols per CTA (col = h*4+g -> 32 hidden cols)
constexpr int BK = 32;               // K per tile (2 mma k16 steps)
constexpr int NT = 4096 / BK;        // 128 k-tiles (64 x/Wx + 64 hx/Wh)
constexpr int NPAIRS = NT / 2;       // 64
constexpr int NUM_NT = (4 * HID) / BN;  // 64 n-tiles
constexpr int GROUP_M = 8;
constexpr int NTHREADS = 512;

// Pre-converted fp16 tensors in the EXACT smem tile image layout:
//   g_a[128 tiles][4096 rows][32 halfs]   (tiles 0..63 = x, 64..127 = hx)
//   g_w[128 tiles][8192 cols][32 halfs]   (col = j*4+gate; tiles 64.. = Wh)
// Within each 64B row: k-permuted + granule-swizzled (see perm below).
__device__ __half g_a[16777216];     // 32 MB
__device__ __half g_w[33554432];     // 64 MB

// ---------------- smem layout (GEMM) ----------------
// 4 pair-slots; tile t -> slot (t>>1)&3, sub (t&1). 8KB per fp16 tile.
constexpr int SM_BASE = 1024;
constexpr int SLOT_B  = 16384;                 // 2 tiles per slot
constexpr int SM_BOFF = SM_BASE + 4 * SLOT_B;  // B region after 64KB of A
constexpr int CSTRIDE = 132;
constexpr int SM_C = 1024;
constexpr int SMEM_TOTAL = SM_BASE + 2 * 4 * SLOT_B;  // 132096; epilogue fits inside

__device__ __forceinline__ float sigm(float v) { return 1.f / (1.f + __expf(-v)); }

// k-permutation within a 64B (32-half) row. For the half2 word m (= k/2):
//   w(m) = (m&3)*4 + ((m>>3)&1)*2 + ((m>>2)&1)
//   stored word index = ((w>>2) ^ sw)*4 + (w&3),  sw = (row>>1)&1
__device__ __forceinline__ int perm_word(int m, int sw) {
    int w = (m & 3) * 4 + ((m >> 3) & 1) * 2 + ((m >> 2) & 1);
    return (((w >> 2) ^ sw) << 2) + (w & 3);
}

// ---------------- convert kernels ----------------
__global__ void convert_a(const float* __restrict__ src, int tbase) {
    int idx = blockIdx.x * blockDim.x + threadIdx.x;   // 64*4096*8
    int kq  = idx & 7;
    int row = (idx >> 3) & 4095;
    int t   = idx >> 15;
    float4 v = *(const float4*)(src + (size_t)row * KHALF + t * BK + kq * 4);
    __half2* dst = (__half2*)(g_a + ((size_t)(tbase + t) * 4096 + row) * 32);
    int sw = (row >> 1) & 1;
    dst[perm_word(2 * kq, sw)]     = __floats2half2_rn(v.x, v.y);
    dst[perm_word(2 * kq + 1, sw)] = __floats2half2_rn(v.z, v.w);
}

__global__ void convert_w(const float* __restrict__ src, int tbase) {
    int idx = blockIdx.x * blockDim.x + threadIdx.x;   // 64*8192*8
    int kq  = idx & 7;
    int c   = (idx >> 3) & 8191;                        // interleaved col = j*4+g
    int t   = idx >> 16;
    int j = c >> 2, gate = c & 3;
    float4 v = *(const float4*)(src + (size_t)(gate * HID + j) * KHALF + t * BK + kq * 4);
    __half2* dst = (__half2*)(g_w + ((size_t)(tbase + t) * 8192 + c) * 32);
    int sw = (c >> 1) & 1;
    dst[perm_word(2 * kq, sw)]     = __floats2half2_rn(v.x, v.y);
    dst[perm_word(2 * kq + 1, sw)] = __floats2half2_rn(v.z, v.w);
}

// ---------------- GEMM helpers ----------------
__device__ __forceinline__ uint32_t s2u(const void* p) {
    uint32_t a;
    asm("{ .reg .u64 t; cvta.to.shared.u64 t, %1; cvt.u32.u64 %0, t; }" : "=r"(a) : "l"(p));
    return a;
}
__device__ __forceinline__ void cpa16(uint32_t s, const void* g) {
    asm volatile("cp.async.cg.shared.global [%0], [%1], 16;" :: "r"(s), "l"(g));
}
__device__ __forceinline__ void mma_f16(float& c0, float& c1, float& c2, float& c3,
                                        uint32_t a0, uint32_t a1, uint32_t a2, uint32_t a3,
                                        uint32_t b0, uint32_t b1) {
    asm volatile(
        "mma.sync.aligned.m16n8k16.row.col.f32.f16.f16.f32 "
        "{%0,%1,%2,%3}, {%4,%5,%6,%7}, {%8,%9}, {%0,%1,%2,%3};"
        : "+f"(c0), "+f"(c1), "+f"(c2), "+f"(c3)
        : "r"(a0), "r"(a1), "r"(a2), "r"(a3), "r"(b0), "r"(b1));
}

// ---------------- GEMM + fused LSTM kernel ----------------
__global__ __launch_bounds__(NTHREADS, 1)
void lstm_gemm(const float* __restrict__ cx,
               const float* __restrict__ bx,
               const float* __restrict__ bh,
               float* __restrict__ out)
{
    extern __shared__ __align__(1024) uint8_t smem[];
    const uint32_t sbase = s2u(smem);
    const int tid  = threadIdx.x;
    const int wid  = tid >> 5;
    const int lane = tid & 31;
    const int g    = lane >> 2;
    const int tig  = lane & 3;

    // ---- CTA tile mapping (GROUP_M swizzle for L2 reuse) ----
    int bid    = blockIdx.x;
    int group  = bid / (GROUP_M * NUM_NT);
    int rem    = bid % (GROUP_M * NUM_NT);
    int m_tile = group * GROUP_M + (rem % GROUP_M);
    int n_tile = rem / GROUP_M;
    const int m0 = m_tile * BM;
    const int j0 = n_tile * (BN / 4);

    // ---- cp.async descriptors: thread copies 16B chunk tid of each 8KB tile ----
    const char* gA0 = (const char*)g_a + (size_t)m0 * 64 + tid * 16;       // + t*4096*64
    const char* gB0 = (const char*)g_w + (size_t)(4 * j0) * 64 + tid * 16; // + t*8192*64

    auto tileA = [&](int t) -> uint32_t { return sbase + SM_BASE + ((t >> 1) & 3) * SLOT_B + (t & 1) * 8192; };
    auto tileB = [&](int t) -> uint32_t { return sbase + SM_BOFF + ((t >> 1) & 3) * SLOT_B + (t & 1) * 8192; };

    auto issue_pair = [&](int p) {
        const int t0 = 2 * p;
#pragma unroll
        for (int s = 0; s < 2; s++) {
            const int t = t0 + s;
            cpa16(tileA(t) + tid * 16, gA0 + (size_t)t * 4096 * 64);
            cpa16(tileB(t) + tid * 16, gB0 + (size_t)t * 8192 * 64);
        }
        asm volatile("cp.async.commit_group;" ::: "memory");
    };

    // ---- warp tile: 4(M) x 4(N) grid, 32x32 per warp ----
    const int wm = (wid >> 2) * 32;
    const int wn = (wid & 3) * 32;
    const int cgo = (tig ^ ((g >> 1) & 1)) << 4;   // fragment granule byte offset

    float acc[2][4][4];
#pragma unroll
    for (int mi = 0; mi < 2; mi++)
#pragma unroll
        for (int ni = 0; ni < 4; ni++)
#pragma unroll
            for (int q = 0; q < 4; q++) acc[mi][ni][q] = 0.f;

    auto mma_tile = [&](int t) {
        const uint8_t* At = smem + (tileA(t) - sbase);
        const uint8_t* Bt = smem + (tileB(t) - sbase);
        uint4 vA[4], vB[4];
#pragma unroll
        for (int mi = 0; mi < 2; mi++) {
            vA[2 * mi]     = *(const uint4*)(At + (wm + mi * 16 + g)     * 64 + cgo);
            vA[2 * mi + 1] = *(const uint4*)(At + (wm + mi * 16 + g + 8) * 64 + cgo);
        }
#pragma unroll
        for (int ni = 0; ni < 4; ni++)
            vB[ni] = *(const uint4*)(Bt + (wn + ni * 8 + g) * 64 + cgo);
#pragma unroll
        for (int mi = 0; mi < 2; mi++)
#pragma unroll
            for (int ni = 0; ni < 4; ni++) {
                mma_f16(acc[mi][ni][0], acc[mi][ni][1], acc[mi][ni][2], acc[mi][ni][3],
                        vA[2*mi].x, vA[2*mi+1].x, vA[2*mi].y, vA[2*mi+1].y,
                        vB[ni].x, vB[ni].y);
                mma_f16(acc[mi][ni][0], acc[mi][ni][1], acc[mi][ni][2], acc[mi][ni][3],
                        vA[2*mi].z, vA[2*mi+1].z, vA[2*mi].w, vA[2*mi+1].w,
                        vB[ni].z, vB[ni].w);
            }
    };

    // ---- prologue: issue pairs 0,1,2 ----
    issue_pair(0);
    issue_pair(1);
    issue_pair(2);

    // ---- mainloop ----
#pragma unroll 1
    for (int p = 0; p < NPAIRS; p++) {
        if (p < NPAIRS - 2)       asm volatile("cp.async.wait_group 2;" ::: "memory");
        else if (p == NPAIRS - 2) asm volatile("cp.async.wait_group 1;" ::: "memory");
        else                      asm volatile("cp.async.wait_group 0;" ::: "memory");
        __syncthreads();
        if (p + 3 < NPAIRS) issue_pair(p + 3);   // slot (p+3)&3 was freed at this barrier
        mma_tile(2 * p);
        mma_tile(2 * p + 1);
    }

    // ---- epilogue: stage C through smem, then fused LSTM math ----
    __syncthreads();
    float* Cs = (float*)(smem + SM_C);
#pragma unroll
    for (int mi = 0; mi < 2; mi++) {
#pragma unroll
        for (int ni = 0; ni < 4; ni++) {
            const int r1 = wm + mi * 16 + g;
            const int c0 = wn + ni * 8 + tig * 2;
            *(float2*)(Cs + r1 * CSTRIDE + c0)       = make_float2(acc[mi][ni][0], acc[mi][ni][1]);
            *(float2*)(Cs + (r1 + 8) * CSTRIDE + c0) = make_float2(acc[mi][ni][2], acc[mi][ni][3]);
        }
    }
    __syncthreads();

    const int j = j0 + lane;
    const float bs0 = bx[0 * HID + j] + bh[0 * HID + j];
    const float bs1 = bx[1 * HID + j] + bh[1 * HID + j];
    const float bs2 = bx[2 * HID + j] + bh[2 * HID + j];
    const float bs3 = bx[3 * HID + j] + bh[3 * HID + j];

#pragma unroll
    for (int i = 0; i < 8; i++) {
        const int rl  = i * 16 + wid;
        const int row = m0 + rl;
        const float4 gv = *(const float4*)(Cs + rl * CSTRIDE + lane * 4);
        const float f_ = sigm (gv.x + bs0);
        const float i_ = sigm (gv.y + bs1);
        const float c_ = tanhf(gv.z + bs2);
        const float o_ = sigm (gv.w + bs3);
        const float cv = cx[(size_t)row * HID + j];
        const float cy = f_ * cv + i_ * c_;
        const float hy = o_ * tanhf(cy);
        out[(size_t)row * HID + j] = hy;
        out[(size_t)BROWS * HID + (size_t)row * HID + j] = cy;
    }
}

extern "C" void kernel_launch(void* const* d_in, const int* in_sizes, int n_in,
                              void* d_out, int out_size)
{
    const float* x  = (const float*)d_in[0];
    const float* hx = (const float*)d_in[1];
    const float* cx = (const float*)d_in[2];
    const float* Wx = (const float*)d_in[3];
    const float* bx = (const float*)d_in[4];
    const float* Wh = (const float*)d_in[5];
    const float* bh = (const float*)d_in[6];
    float* out = (float*)d_out;

    cudaFuncSetAttribute(lstm_gemm,
                         cudaFuncAttributeMaxDynamicSharedMemorySize, SMEM_TOTAL);

    convert_a<<<8192,  256>>>(x,  0);
    convert_a<<<8192,  256>>>(hx, 64);
    convert_w<<<16384, 256>>>(Wx, 0);
    convert_w<<<16384, 256>>>(Wh, 64);

    const int grid = (BROWS / BM) * NUM_NT;   // 2048
    lstm_gemm<<<grid, NTHREADS, SMEM_TOTAL>>>(cx, bx, bh, out);
}

// round 12
// speedup vs baseline: 3.9003x; 1.2211x over previous
#include <cuda_runtime.h>
#include <cuda_fp16.h>
#include <cstdint>
#include <math.h>

// ---------------- problem constants ----------------
#define HID    2048
#define BROWS  4096
#define KHALF  2048

constexpr int BM = 128;
constexpr int BN = 128;              // C cols per CTA (col = h*4+g -> 32 hidden cols)
constexpr int BK = 32;               // K per tile (2 mma k16 steps)
constexpr int NT = 4096 / BK;        // 128 k-tiles (64 x/Wx + 64 hx/Wh)
constexpr int NPAIRS = NT / 2;       // 64
constexpr int NUM_NT = (4 * HID) / BN;  // 64 n-tiles
constexpr int GROUP_M = 8;
constexpr int NTHREADS = 256;        // 8 warps, 2 CTAs/SM

// Pre-converted fp16 tensors in the EXACT smem tile image layout:
//   g_a[128 tiles][4096 rows][32 halfs]   (tiles 0..63 = x, 64..127 = hx)
//   g_w[128 tiles][8192 cols][32 halfs]   (col = j*4+gate; tiles 64.. = Wh)
__device__ __half g_a[16777216];     // 32 MB
__device__ __half g_w[33554432];     // 64 MB

// ---------------- smem layout (GEMM) ----------------
// SIX tile-slots per operand (ring): tile t -> slot t % 6. 8KB per fp16 tile.
// Depth-3 pair pipeline: pairs p, p+1, p+2 occupy all 6 slots; pair p+3 is
// issued only AFTER the post-mma barrier of pair p (its slots are then free).
constexpr int TILE_BH = 8192;
constexpr int SM_A0 = 1024;                      // A: 6 slots = 48KB
constexpr int SM_B0 = SM_A0 + 6 * TILE_BH;       // B: 6 slots = 48KB (ends 99328)
constexpr int CSTRIDE = 132;
constexpr int SM_C = 1024;                       // epilogue reuses tile region
constexpr int SMEM_TOTAL = SM_B0 + 6 * TILE_BH;  // 99328 (> epilogue 68608)

__device__ __forceinline__ float sigm(float v) { return 1.f / (1.f + __expf(-v)); }

// k-permutation within a 64B (32-half) row (word m = k/2):
__device__ __forceinline__ int perm_word(int m, int sw) {
    int w = (m & 3) * 4 + ((m >> 3) & 1) * 2 + ((m >> 2) & 1);
    return (((w >> 2) ^ sw) << 2) + (w & 3);
}

// ---------------- convert kernels ----------------
__global__ void convert_a(const float* __restrict__ src, int tbase) {
    int idx = blockIdx.x * blockDim.x + threadIdx.x;   // 64*4096*8
    int kq  = idx & 7;
    int row = (idx >> 3) & 4095;
    int t   = idx >> 15;
    float4 v = *(const float4*)(src + (size_t)row * KHALF + t * BK + kq * 4);
    __half2* dst = (__half2*)(g_a + ((size_t)(tbase + t) * 4096 + row) * 32);
    int sw = (row >> 1) & 1;
    dst[perm_word(2 * kq, sw)]     = __floats2half2_rn(v.x, v.y);
    dst[perm_word(2 * kq + 1, sw)] = __floats2half2_rn(v.z, v.w);
}

__global__ void convert_w(const float* __restrict__ src, int tbase) {
    int idx = blockIdx.x * blockDim.x + threadIdx.x;   // 64*8192*8
    int kq  = idx & 7;
    int c   = (idx >> 3) & 8191;                        // interleaved col = j*4+g
    int t   = idx >> 16;
    int j = c >> 2, gate = c & 3;
    float4 v = *(const float4*)(src + (size_t)(gate * HID + j) * KHALF + t * BK + kq * 4);
    __half2* dst = (__half2*)(g_w + ((size_t)(tbase + t) * 8192 + c) * 32);
    int sw = (c >> 1) & 1;
    dst[perm_word(2 * kq, sw)]     = __floats2half2_rn(v.x, v.y);
    dst[perm_word(2 * kq + 1, sw)] = __floats2half2_rn(v.z, v.w);
}

// ---------------- GEMM helpers ----------------
__device__ __forceinline__ uint32_t s2u(const void* p) {
    uint32_t a;
    asm("{ .reg .u64 t; cvta.to.shared.u64 t, %1; cvt.u32.u64 %0, t; }" : "=r"(a) : "l"(p));
    return a;
}
__device__ __forceinline__ void cpa16(uint32_t s, const void* g) {
    asm volatile("cp.async.cg.shared.global [%0], [%1], 16;" :: "r"(s), "l"(g));
}
__device__ __forceinline__ void mma_f16(float& c0, float& c1, float& c2, float& c3,
                                        uint32_t a0, uint32_t a1, uint32_t a2, uint32_t a3,
                                        uint32_t b0, uint32_t b1) {
    asm volatile(
        "mma.sync.aligned.m16n8k16.row.col.f32.f16.f16.f32 "
        "{%0,%1,%2,%3}, {%4,%5,%6,%7}, {%8,%9}, {%0,%1,%2,%3};"
        : "+f"(c0), "+f"(c1), "+f"(c2), "+f"(c3)
        : "r"(a0), "r"(a1), "r"(a2), "r"(a3), "r"(b0), "r"(b1));
}

// ---------------- GEMM + fused LSTM kernel ----------------
__global__ __launch_bounds__(NTHREADS, 2)
void lstm_gemm(const float* __restrict__ cx,
               const float* __restrict__ bx,
               const float* __restrict__ bh,
               float* __restrict__ out)
{
    extern __shared__ __align__(1024) uint8_t smem[];
    const uint32_t sbase = s2u(smem);
    const int tid  = threadIdx.x;
    const int wid  = tid >> 5;    // 0..7
    const int lane = tid & 31;
    const int g    = lane >> 2;
    const int tig  = lane & 3;

    // ---- CTA tile mapping (GROUP_M swizzle for L2 reuse) ----
    int bid    = blockIdx.x;
    int group  = bid / (GROUP_M * NUM_NT);
    int rem    = bid % (GROUP_M * NUM_NT);
    int m_tile = group * GROUP_M + (rem % GROUP_M);
    int n_tile = rem / GROUP_M;
    const int m0 = m_tile * BM;
    const int j0 = n_tile * (BN / 4);

    // ---- cp.async: thread copies chunks tid, tid+256 of each 8KB tile ----
    const char* gA0 = (const char*)g_a + (size_t)m0 * 64;        // + t*4096*64
    const char* gB0 = (const char*)g_w + (size_t)(4 * j0) * 64;  // + t*8192*64

    auto issue_pair = [&](int p) {
        const int t0 = 2 * p;
#pragma unroll
        for (int s = 0; s < 2; s++) {
            const int t  = t0 + s;
            const int sl = t % 6;
            const uint32_t sa = sbase + SM_A0 + sl * TILE_BH;
            const uint32_t sb = sbase + SM_B0 + sl * TILE_BH;
            const char* ga = gA0 + (size_t)t * 4096 * 64;
            const char* gb = gB0 + (size_t)t * 8192 * 64;
            cpa16(sa + tid * 16,        ga + tid * 16);
            cpa16(sa + tid * 16 + 4096, ga + tid * 16 + 4096);
            cpa16(sb + tid * 16,        gb + tid * 16);
            cpa16(sb + tid * 16 + 4096, gb + tid * 16 + 4096);
        }
        asm volatile("cp.async.commit_group;" ::: "memory");
    };

    // ---- warp tile: 2(M) x 4(N) grid, 64x32 per warp ----
    const int wm = (wid >> 2) * 64;
    const int wn = (wid & 3) * 32;
    const int cgo = (tig ^ ((g >> 1) & 1)) << 4;   // fragment granule byte offset

    float acc[4][4][4];
#pragma unroll
    for (int mi = 0; mi < 4; mi++)
#pragma unroll
        for (int ni = 0; ni < 4; ni++)
#pragma unroll
            for (int q = 0; q < 4; q++) acc[mi][ni][q] = 0.f;

    auto mma_tile = [&](int t) {
        const int sl = t % 6;
        const uint8_t* At = smem + SM_A0 + sl * TILE_BH;
        const uint8_t* Bt = smem + SM_B0 + sl * TILE_BH;
        uint4 vB[4];
#pragma unroll
        for (int ni = 0; ni < 4; ni++)
            vB[ni] = *(const uint4*)(Bt + (wn + ni * 8 + g) * 64 + cgo);
#pragma unroll
        for (int mi = 0; mi < 4; mi++) {
            uint4 vA0 = *(const uint4*)(At + (wm + mi * 16 + g)     * 64 + cgo);
            uint4 vA1 = *(const uint4*)(At + (wm + mi * 16 + g + 8) * 64 + cgo);
#pragma unroll
            for (int ni = 0; ni < 4; ni++) {
                mma_f16(acc[mi][ni][0], acc[mi][ni][1], acc[mi][ni][2], acc[mi][ni][3],
                        vA0.x, vA1.x, vA0.y, vA1.y, vB[ni].x, vB[ni].y);
                mma_f16(acc[mi][ni][0], acc[mi][ni][1], acc[mi][ni][2], acc[mi][ni][3],
                        vA0.z, vA1.z, vA0.w, vA1.w, vB[ni].z, vB[ni].w);
            }
        }
    };

    // ---- prologue: issue pairs 0,1,2 (fills all 6 slots) ----
    issue_pair(0);
    issue_pair(1);
    issue_pair(2);

    // ---- mainloop: consume pair p, then refill its slots with pair p+3 ----
#pragma unroll 1
    for (int p = 0; p < NPAIRS; p++) {
        if (p < NPAIRS - 2)       asm volatile("cp.async.wait_group 2;" ::: "memory");
        else if (p == NPAIRS - 2) asm volatile("cp.async.wait_group 1;" ::: "memory");
        else                      asm volatile("cp.async.wait_group 0;" ::: "memory");
        __syncthreads();                       // pair p visible to all warps
        mma_tile(2 * p);
        mma_tile(2 * p + 1);
        if (p + 3 < NPAIRS) {
            __syncthreads();                   // all warps done reading pair p
            issue_pair(p + 3);                 // lands in pair p's freed slots
        }
    }

    // ---- epilogue: stage C through smem, then fused LSTM math ----
    __syncthreads();
    float* Cs = (float*)(smem + SM_C);
#pragma unroll
    for (int mi = 0; mi < 4; mi++) {
#pragma unroll
        for (int ni = 0; ni < 4; ni++) {
            const int r1 = wm + mi * 16 + g;
            const int c0 = wn + ni * 8 + tig * 2;
            *(float2*)(Cs + r1 * CSTRIDE + c0)       = make_float2(acc[mi][ni][0], acc[mi][ni][1]);
            *(float2*)(Cs + (r1 + 8) * CSTRIDE + c0) = make_float2(acc[mi][ni][2], acc[mi][ni][3]);
        }
    }
    __syncthreads();

    const int j = j0 + lane;
    const float bs0 = bx[0 * HID + j] + bh[0 * HID + j];
    const float bs1 = bx[1 * HID + j] + bh[1 * HID + j];
    const float bs2 = bx[2 * HID + j] + bh[2 * HID + j];
    const float bs3 = bx[3 * HID + j] + bh[3 * HID + j];

#pragma unroll
    for (int i = 0; i < 16; i++) {
        const int rl  = i * 8 + wid;          // local row 0..127
        const int row = m0 + rl;
        const float4 gv = *(const float4*)(Cs + rl * CSTRIDE + lane * 4);
        const float f_ = sigm (gv.x + bs0);
        const float i_ = sigm (gv.y + bs1);
        const float c_ = tanhf(gv.z + bs2);
        const float o_ = sigm (gv.w + bs3);
        const float cv = cx[(size_t)row * HID + j];
        const float cy = f_ * cv + i_ * c_;
        const float hy = o_ * tanhf(cy);
        out[(size_t)row * HID + j] = hy;
        out[(size_t)BROWS * HID + (size_t)row * HID + j] = cy;
    }
}

extern "C" void kernel_launch(void* const* d_in, const int* in_sizes, int n_in,
                              void* d_out, int out_size)
{
    const float* x  = (const float*)d_in[0];
    const float* hx = (const float*)d_in[1];
    const float* cx = (const float*)d_in[2];
    const float* Wx = (const float*)d_in[3];
    const float* bx = (const float*)d_in[4];
    const float* Wh = (const float*)d_in[5];
    const float* bh = (const float*)d_in[6];
    float* out = (float*)d_out;

    cudaFuncSetAttribute(lstm_gemm,
                         cudaFuncAttributeMaxDynamicSharedMemorySize, SMEM_TOTAL);

    convert_a<<<8192,  256>>>(x,  0);
    convert_a<<<8192,  256>>>(hx, 64);
    convert_w<<<16384, 256>>>(Wx, 0);
    convert_w<<<16384, 256>>>(Wh, 64);

    const int grid = (BROWS / BM) * NUM_NT;   // 2048
    lstm_gemm<<<grid, NTHREADS, SMEM_TOTAL>>>(cx, bx, bh, out);
}

// round 13
// speedup vs baseline: 4.0767x; 1.0452x over previous
#include <cuda_runtime.h>
#include <cuda_fp16.h>
#include <cstdint>
#include <math.h>

// ---------------- problem constants ----------------
#define HID    2048
#define BROWS  4096
#define KHALF  2048

constexpr int BM = 128;
constexpr int BN = 128;              // C cols per CTA (col = h*4+g -> 32 hidden cols)
constexpr int BK = 32;               // K per tile (2 mma k16 steps)
constexpr int NT = 4096 / BK;        // 128 k-tiles
constexpr int NPAIRS = NT / 2;       // 64
constexpr int NUM_NT = (4 * HID) / BN;  // 64 n-tiles
constexpr int GROUP_M = 8;
constexpr int NTHREADS = 256;        // 8 warps, 2 CTAs/SM

// Pre-converted fp16 tensors in the EXACT smem tile image layout.
__device__ __half g_a[16777216];     // 32 MB: [128 tiles][4096 rows][32 halfs]
__device__ __half g_w[33554432];     // 64 MB: [128 tiles][8192 cols][32 halfs]

// ---------------- smem layout (GEMM) ----------------
// SIX tile-slots per operand; pair p occupies slots (2p)%6,(2p+1)%6 (period 3).
constexpr int TILE_BH = 8192;
constexpr int SM_A0 = 1024;                      // A: 6 slots = 48KB
constexpr int SM_B0 = SM_A0 + 6 * TILE_BH;       // B: 6 slots = 48KB
constexpr int CSTRIDE = 132;
constexpr int SM_C = 1024;
constexpr int SMEM_TOTAL = SM_B0 + 6 * TILE_BH;  // 99328

constexpr size_t A_TSTRIDE = 4096 * 64;          // bytes per A k-tile
constexpr size_t B_TSTRIDE = 8192 * 64;          // bytes per B k-tile

__device__ __forceinline__ float sigm(float v) { return 1.f / (1.f + __expf(-v)); }

__device__ __forceinline__ int perm_word(int m, int sw) {
    int w = (m & 3) * 4 + ((m >> 3) & 1) * 2 + ((m >> 2) & 1);
    return (((w >> 2) ^ sw) << 2) + (w & 3);
}

// ---------------- convert kernels ----------------
__global__ void convert_a(const float* __restrict__ src, int tbase) {
    int idx = blockIdx.x * blockDim.x + threadIdx.x;
    int kq  = idx & 7;
    int row = (idx >> 3) & 4095;
    int t   = idx >> 15;
    float4 v = *(const float4*)(src + (size_t)row * KHALF + t * BK + kq * 4);
    __half2* dst = (__half2*)(g_a + ((size_t)(tbase + t) * 4096 + row) * 32);
    int sw = (row >> 1) & 1;
    dst[perm_word(2 * kq, sw)]     = __floats2half2_rn(v.x, v.y);
    dst[perm_word(2 * kq + 1, sw)] = __floats2half2_rn(v.z, v.w);
}

__global__ void convert_w(const float* __restrict__ src, int tbase) {
    int idx = blockIdx.x * blockDim.x + threadIdx.x;
    int kq  = idx & 7;
    int c   = (idx >> 3) & 8191;
    int t   = idx >> 16;
    int j = c >> 2, gate = c & 3;
    float4 v = *(const float4*)(src + (size_t)(gate * HID + j) * KHALF + t * BK + kq * 4);
    __half2* dst = (__half2*)(g_w + ((size_t)(tbase + t) * 8192 + c) * 32);
    int sw = (c >> 1) & 1;
    dst[perm_word(2 * kq, sw)]     = __floats2half2_rn(v.x, v.y);
    dst[perm_word(2 * kq + 1, sw)] = __floats2half2_rn(v.z, v.w);
}

// ---------------- GEMM helpers ----------------
__device__ __forceinline__ uint32_t s2u(const void* p) {
    uint32_t a;
    asm("{ .reg .u64 t; cvta.to.shared.u64 t, %1; cvt.u32.u64 %0, t; }" : "=r"(a) : "l"(p));
    return a;
}
__device__ __forceinline__ void cpa16(uint32_t s, const void* g) {
    asm volatile("cp.async.cg.shared.global [%0], [%1], 16;" :: "r"(s), "l"(g));
}
__device__ __forceinline__ void mma_f16(float& c0, float& c1, float& c2, float& c3,
                                        uint32_t a0, uint32_t a1, uint32_t a2, uint32_t a3,
                                        uint32_t b0, uint32_t b1) {
    asm volatile(
        "mma.sync.aligned.m16n8k16.row.col.f32.f16.f16.f32 "
        "{%0,%1,%2,%3}, {%4,%5,%6,%7}, {%8,%9}, {%0,%1,%2,%3};"
        : "+f"(c0), "+f"(c1), "+f"(c2), "+f"(c3)
        : "r"(a0), "r"(a1), "r"(a2), "r"(a3), "r"(b0), "r"(b1));
}

// ---------------- GEMM + fused LSTM kernel ----------------
__global__ __launch_bounds__(NTHREADS, 2)
void lstm_gemm(const float* __restrict__ cx,
               const float* __restrict__ bx,
               const float* __restrict__ bh,
               float* __restrict__ out)
{
    extern __shared__ __align__(1024) uint8_t smem[];
    const uint32_t sbase = s2u(smem);
    const int tid  = threadIdx.x;
    const int wid  = tid >> 5;
    const int lane = tid & 31;
    const int g    = lane >> 2;
    const int tig  = lane & 3;

    // ---- CTA tile mapping ----
    int bid    = blockIdx.x;
    int group  = bid / (GROUP_M * NUM_NT);
    int rem    = bid % (GROUP_M * NUM_NT);
    int m_tile = group * GROUP_M + (rem % GROUP_M);
    int n_tile = rem / GROUP_M;
    const int m0 = m_tile * BM;
    const int j0 = n_tile * (BN / 4);

    // ---- per-thread cp.async source pointers (carried, constant strides) ----
    const char* gA = (const char*)g_a + (size_t)m0 * 64 + tid * 16;
    const char* gB = (const char*)g_w + (size_t)(4 * j0) * 64 + tid * 16;

    // issue pair whose tiles go to smem slots s0=2q, s1=2q+1 (compile-time),
    // reading from carried pointers (advanced by caller).
    auto issue_pair_at = [&](int s0, const char* ga, const char* gb) {
#pragma unroll
        for (int s = 0; s < 2; s++) {
            const uint32_t sa = sbase + SM_A0 + (s0 + s) * TILE_BH;
            const uint32_t sb = sbase + SM_B0 + (s0 + s) * TILE_BH;
            const char* gat = ga + s * A_TSTRIDE;
            const char* gbt = gb + s * B_TSTRIDE;
            cpa16(sa + tid * 16,        gat);
            cpa16(sa + tid * 16 + 4096, gat + 4096);
            cpa16(sb + tid * 16,        gbt);
            cpa16(sb + tid * 16 + 4096, gbt + 4096);
        }
        asm volatile("cp.async.commit_group;" ::: "memory");
    };

    // ---- warp tile: 2(M) x 4(N), 64x32 per warp ----
    const int wm = (wid >> 2) * 64;
    const int wn = (wid & 3) * 32;
    const int cgo = (tig ^ ((g >> 1) & 1)) << 4;

    float acc[4][4][4];
#pragma unroll
    for (int mi = 0; mi < 4; mi++)
#pragma unroll
        for (int ni = 0; ni < 4; ni++)
#pragma unroll
            for (int q = 0; q < 4; q++) acc[mi][ni][q] = 0.f;

    auto mma_slot = [&](int sl) {
        const uint8_t* At = smem + SM_A0 + sl * TILE_BH;
        const uint8_t* Bt = smem + SM_B0 + sl * TILE_BH;
        uint4 vB[4];
#pragma unroll
        for (int ni = 0; ni < 4; ni++)
            vB[ni] = *(const uint4*)(Bt + (wn + ni * 8 + g) * 64 + cgo);
#pragma unroll
        for (int mi = 0; mi < 4; mi++) {
            uint4 vA0 = *(const uint4*)(At + (wm + mi * 16 + g)     * 64 + cgo);
            uint4 vA1 = *(const uint4*)(At + (wm + mi * 16 + g + 8) * 64 + cgo);
#pragma unroll
            for (int ni = 0; ni < 4; ni++) {
                mma_f16(acc[mi][ni][0], acc[mi][ni][1], acc[mi][ni][2], acc[mi][ni][3],
                        vA0.x, vA1.x, vA0.y, vA1.y, vB[ni].x, vB[ni].y);
                mma_f16(acc[mi][ni][0], acc[mi][ni][1], acc[mi][ni][2], acc[mi][ni][3],
                        vA0.z, vA1.z, vA0.w, vA1.w, vB[ni].z, vB[ni].w);
            }
        }
    };

    // ---- prologue: issue pairs 0,1,2 (slots 0/1, 2/3, 4/5) ----
    issue_pair_at(0, gA, gB);
    issue_pair_at(2, gA + 2 * A_TSTRIDE, gB + 2 * B_TSTRIDE);
    issue_pair_at(4, gA + 4 * A_TSTRIDE, gB + 4 * B_TSTRIDE);
    // carried pointers for the NEXT pair to be issued (pair 3)
    const char* gAn = gA + 6 * A_TSTRIDE;
    const char* gBn = gB + 6 * B_TSTRIDE;

    // ---- mainloop: 21 blocks x 3 pairs (pairs 0..62), slots compile-time ----
#pragma unroll 1
    for (int blk = 0; blk < 21; blk++) {
        const int pbase = 3 * blk;
#pragma unroll
        for (int q = 0; q < 3; q++) {
            const int p  = pbase + q;
            const int s0 = 2 * q;                 // compile-time slot base
            if (p < NPAIRS - 2)
                asm volatile("cp.async.wait_group 2;" ::: "memory");
            else
                asm volatile("cp.async.wait_group 1;" ::: "memory");
            __syncthreads();
            mma_slot(s0);
            mma_slot(s0 + 1);
            if (p + 3 < NPAIRS) {
                __syncthreads();                  // all warps done with pair p
                issue_pair_at(s0, gAn, gBn);      // pair p+3 -> same slots
                gAn += 2 * A_TSTRIDE;
                gBn += 2 * B_TSTRIDE;
            }
        }
    }
    // ---- tail: pair 63 (slots 0,1) ----
    asm volatile("cp.async.wait_group 0;" ::: "memory");
    __syncthreads();
    mma_slot(0);
    mma_slot(1);

    // ---- epilogue: stage C through smem, then fused LSTM math ----
    __syncthreads();
    float* Cs = (float*)(smem + SM_C);
#pragma unroll
    for (int mi = 0; mi < 4; mi++) {
#pragma unroll
        for (int ni = 0; ni < 4; ni++) {
            const int r1 = wm + mi * 16 + g;
            const int c0 = wn + ni * 8 + tig * 2;
            *(float2*)(Cs + r1 * CSTRIDE + c0)       = make_float2(acc[mi][ni][0], acc[mi][ni][1]);
            *(float2*)(Cs + (r1 + 8) * CSTRIDE + c0) = make_float2(acc[mi][ni][2], acc[mi][ni][3]);
        }
    }
    __syncthreads();

    const int j = j0 + lane;
    const float bs0 = bx[0 * HID + j] + bh[0 * HID + j];
    const float bs1 = bx[1 * HID + j] + bh[1 * HID + j];
    const float bs2 = bx[2 * HID + j] + bh[2 * HID + j];
    const float bs3 = bx[3 * HID + j] + bh[3 * HID + j];

#pragma unroll
    for (int i = 0; i < 16; i++) {
        const int rl  = i * 8 + wid;
        const int row = m0 + rl;
        const float4 gv = *(const float4*)(Cs + rl * CSTRIDE + lane * 4);
        const float f_ = sigm (gv.x + bs0);
        const float i_ = sigm (gv.y + bs1);
        const float c_ = tanhf(gv.z + bs2);
        const float o_ = sigm (gv.w + bs3);
        const float cv = cx[(size_t)row * HID + j];
        const float cy = f_ * cv + i_ * c_;
        const float hy = o_ * tanhf(cy);
        out[(size_t)row * HID + j] = hy;
        out[(size_t)BROWS * HID + (size_t)row * HID + j] = cy;
    }
}

extern "C" void kernel_launch(void* const* d_in, const int* in_sizes, int n_in,
                              void* d_out, int out_size)
{
    const float* x  = (const float*)d_in[0];
    const float* hx = (const float*)d_in[1];
    const float* cx = (const float*)d_in[2];
    const float* Wx = (const float*)d_in[3];
    const float* bx = (const float*)d_in[4];
    const float* Wh = (const float*)d_in[5];
    const float* bh = (const float*)d_in[6];
    float* out = (float*)d_out;

    cudaFuncSetAttribute(lstm_gemm,
                         cudaFuncAttributeMaxDynamicSharedMemorySize, SMEM_TOTAL);

    convert_a<<<8192,  256>>>(x,  0);
    convert_a<<<8192,  256>>>(hx, 64);
    convert_w<<<16384, 256>>>(Wx, 0);
    convert_w<<<16384, 256>>>(Wh, 64);

    const int grid = (BROWS / BM) * NUM_NT;   // 2048
    lstm_gemm<<<grid, NTHREADS, SMEM_TOTAL>>>(cx, bx, bh, out);
}

// round 14
// speedup vs baseline: 4.1228x; 1.0113x over previous
#include <cuda_runtime.h>
#include <cuda_fp16.h>
#include <cstdint>
#include <math.h>

// ---------------- problem constants ----------------
#define HID    2048
#define BROWS  4096
#define KHALF  2048

constexpr int BM = 128;
constexpr int BN = 128;              // C cols per CTA (col = h*4+g -> 32 hidden cols)
constexpr int BK = 32;               // K per tile (2 mma k16 steps)
constexpr int NT = 4096 / BK;        // 128 k-tiles
constexpr int NPAIRS = NT / 2;       // 64
constexpr int NUM_NT = (4 * HID) / BN;  // 64 n-tiles
constexpr int GROUP_M = 8;
constexpr int NTHREADS = 256;        // 8 warps, 2 CTAs/SM

// Pre-converted fp16 tensors in the EXACT smem tile image layout.
__device__ __half g_a[16777216];     // 32 MB: [128 tiles][4096 rows][32 halfs]
__device__ __half g_w[33554432];     // 64 MB: [128 tiles][8192 cols][32 halfs]

// ---------------- smem layout (GEMM) ----------------
// SIX tile-slots per operand; pair p occupies slots (2p)%6,(2p+1)%6 (period 3).
constexpr int TILE_BH = 8192;
constexpr int SM_A0 = 1024;                      // A: 6 slots = 48KB
constexpr int SM_B0 = SM_A0 + 6 * TILE_BH;       // B: 6 slots = 48KB
constexpr int CSTRIDE = 132;
constexpr int SM_C = 1024;
constexpr int SMEM_TOTAL = SM_B0 + 6 * TILE_BH;  // 99328

constexpr size_t A_TSTRIDE = 4096 * 64;          // bytes per A k-tile
constexpr size_t B_TSTRIDE = 8192 * 64;          // bytes per B k-tile

__device__ __forceinline__ float sigm(float v) { return 1.f / (1.f + __expf(-v)); }

__device__ __forceinline__ int perm_word(int m, int sw) {
    int w = (m & 3) * 4 + ((m >> 3) & 1) * 2 + ((m >> 2) & 1);
    return (((w >> 2) ^ sw) << 2) + (w & 3);
}

// ---------------- convert kernels (merged: blockIdx.y picks the half) ----------------
__global__ void convert_a(const float* __restrict__ src0, const float* __restrict__ src1) {
    const float* src = blockIdx.y ? src1 : src0;
    int tbase = blockIdx.y ? 64 : 0;
    int idx = blockIdx.x * blockDim.x + threadIdx.x;
    int kq  = idx & 7;
    int row = (idx >> 3) & 4095;
    int t   = idx >> 15;
    float4 v = *(const float4*)(src + (size_t)row * KHALF + t * BK + kq * 4);
    __half2* dst = (__half2*)(g_a + ((size_t)(tbase + t) * 4096 + row) * 32);
    int sw = (row >> 1) & 1;
    dst[perm_word(2 * kq, sw)]     = __floats2half2_rn(v.x, v.y);
    dst[perm_word(2 * kq + 1, sw)] = __floats2half2_rn(v.z, v.w);
}

__global__ void convert_w(const float* __restrict__ src0, const float* __restrict__ src1) {
    const float* src = blockIdx.y ? src1 : src0;
    int tbase = blockIdx.y ? 64 : 0;
    int idx = blockIdx.x * blockDim.x + threadIdx.x;
    int kq  = idx & 7;
    int c   = (idx >> 3) & 8191;
    int t   = idx >> 16;
    int j = c >> 2, gate = c & 3;
    float4 v = *(const float4*)(src + (size_t)(gate * HID + j) * KHALF + t * BK + kq * 4);
    __half2* dst = (__half2*)(g_w + ((size_t)(tbase + t) * 8192 + c) * 32);
    int sw = (c >> 1) & 1;
    dst[perm_word(2 * kq, sw)]     = __floats2half2_rn(v.x, v.y);
    dst[perm_word(2 * kq + 1, sw)] = __floats2half2_rn(v.z, v.w);
}

// ---------------- GEMM helpers ----------------
__device__ __forceinline__ uint32_t s2u(const void* p) {
    uint32_t a;
    asm("{ .reg .u64 t; cvta.to.shared.u64 t, %1; cvt.u32.u64 %0, t; }" : "=r"(a) : "l"(p));
    return a;
}
__device__ __forceinline__ void cpa16(uint32_t s, const void* g) {
    asm volatile("cp.async.cg.shared.global [%0], [%1], 16;" :: "r"(s), "l"(g));
}
__device__ __forceinline__ void mma_f16(float& c0, float& c1, float& c2, float& c3,
                                        uint32_t a0, uint32_t a1, uint32_t a2, uint32_t a3,
                                        uint32_t b0, uint32_t b1) {
    asm volatile(
        "mma.sync.aligned.m16n8k16.row.col.f32.f16.f16.f32 "
        "{%0,%1,%2,%3}, {%4,%5,%6,%7}, {%8,%9}, {%0,%1,%2,%3};"
        : "+f"(c0), "+f"(c1), "+f"(c2), "+f"(c3)
        : "r"(a0), "r"(a1), "r"(a2), "r"(a3), "r"(b0), "r"(b1));
}

// ---------------- GEMM + fused LSTM kernel ----------------
__global__ __launch_bounds__(NTHREADS, 2)
void lstm_gemm(const float* __restrict__ cx,
               const float* __restrict__ bx,
               const float* __restrict__ bh,
               float* __restrict__ out)
{
    extern __shared__ __align__(1024) uint8_t smem[];
    const uint32_t sbase = s2u(smem);
    const int tid  = threadIdx.x;
    const int wid  = tid >> 5;
    const int lane = tid & 31;
    const int g    = lane >> 2;
    const int tig  = lane & 3;

    // ---- CTA tile mapping ----
    int bid    = blockIdx.x;
    int group  = bid / (GROUP_M * NUM_NT);
    int rem    = bid % (GROUP_M * NUM_NT);
    int m_tile = group * GROUP_M + (rem % GROUP_M);
    int n_tile = rem / GROUP_M;
    const int m0 = m_tile * BM;
    const int j0 = n_tile * (BN / 4);

    // ---- per-thread cp.async source pointers ----
    const char* gA = (const char*)g_a + (size_t)m0 * 64 + tid * 16;
    const char* gB = (const char*)g_w + (size_t)(4 * j0) * 64 + tid * 16;

    auto issue_pair_at = [&](int s0, const char* ga, const char* gb) {
#pragma unroll
        for (int s = 0; s < 2; s++) {
            const uint32_t sa = sbase + SM_A0 + (s0 + s) * TILE_BH;
            const uint32_t sb = sbase + SM_B0 + (s0 + s) * TILE_BH;
            const char* gat = ga + s * A_TSTRIDE;
            const char* gbt = gb + s * B_TSTRIDE;
            cpa16(sa + tid * 16,        gat);
            cpa16(sa + tid * 16 + 4096, gat + 4096);
            cpa16(sb + tid * 16,        gbt);
            cpa16(sb + tid * 16 + 4096, gbt + 4096);
        }
        asm volatile("cp.async.commit_group;" ::: "memory");
    };

    // ---- warp tile: 2(M) x 4(N), 64x32 per warp ----
    const int wm = (wid >> 2) * 64;
    const int wn = (wid & 3) * 32;
    const int cgo = (tig ^ ((g >> 1) & 1)) << 4;

    float acc[4][4][4];
#pragma unroll
    for (int mi = 0; mi < 4; mi++)
#pragma unroll
        for (int ni = 0; ni < 4; ni++)
#pragma unroll
            for (int q = 0; q < 4; q++) acc[mi][ni][q] = 0.f;

    auto mma_slot = [&](int sl) {
        const uint8_t* At = smem + SM_A0 + sl * TILE_BH;
        const uint8_t* Bt = smem + SM_B0 + sl * TILE_BH;
        uint4 vB[4];
#pragma unroll
        for (int ni = 0; ni < 4; ni++)
            vB[ni] = *(const uint4*)(Bt + (wn + ni * 8 + g) * 64 + cgo);
#pragma unroll
        for (int mi = 0; mi < 4; mi++) {
            uint4 vA0 = *(const uint4*)(At + (wm + mi * 16 + g)     * 64 + cgo);
            uint4 vA1 = *(const uint4*)(At + (wm + mi * 16 + g + 8) * 64 + cgo);
#pragma unroll
            for (int ni = 0; ni < 4; ni++) {
                mma_f16(acc[mi][ni][0], acc[mi][ni][1], acc[mi][ni][2], acc[mi][ni][3],
                        vA0.x, vA1.x, vA0.y, vA1.y, vB[ni].x, vB[ni].y);
                mma_f16(acc[mi][ni][0], acc[mi][ni][1], acc[mi][ni][2], acc[mi][ni][3],
                        vA0.z, vA1.z, vA0.w, vA1.w, vB[ni].z, vB[ni].w);
            }
        }
    };

    // ---- prologue: issue pairs 0 (slots 0/1) and 1 (slots 2/3) ----
    issue_pair_at(0, gA, gB);
    issue_pair_at(2, gA + 2 * A_TSTRIDE, gB + 2 * B_TSTRIDE);
    const char* gAn = gA + 4 * A_TSTRIDE;   // next pair to issue: pair 2
    const char* gBn = gB + 4 * B_TSTRIDE;

    // ---- mainloop: ONE sync per pair; issue pair p+2 into slot (p-1)%3 ----
    // pairs 0..62 in 21 blocks of 3 (slots compile-time), pair 63 in tail.
#pragma unroll 1
    for (int blk = 0; blk < 21; blk++) {
        const int pbase = 3 * blk;
#pragma unroll
        for (int q = 0; q < 3; q++) {
            const int p   = pbase + q;
            const int s0  = 2 * q;                    // this pair's slots
            const int sis = 2 * ((q + 2) % 3);        // issue target = (p-1)%3 slots
            asm volatile("cp.async.wait_group 1;" ::: "memory");
            __syncthreads();                          // mma p-1 done by ALL warps
            if (p + 2 < NPAIRS) {
                issue_pair_at(sis, gAn, gBn);         // pair p+2 -> freed slots
                gAn += 2 * A_TSTRIDE;
                gBn += 2 * B_TSTRIDE;
            }
            mma_slot(s0);
            mma_slot(s0 + 1);
        }
    }
    // ---- tail: pair 63 (slots 0,1) ----
    asm volatile("cp.async.wait_group 0;" ::: "memory");
    __syncthreads();
    mma_slot(0);
    mma_slot(1);

    // ---- epilogue: stage C through smem, then fused LSTM math ----
    __syncthreads();
    float* Cs = (float*)(smem + SM_C);
#pragma unroll
    for (int mi = 0; mi < 4; mi++) {
#pragma unroll
        for (int ni = 0; ni < 4; ni++) {
            const int r1 = wm + mi * 16 + g;
            const int c0 = wn + ni * 8 + tig * 2;
            *(float2*)(Cs + r1 * CSTRIDE + c0)       = make_float2(acc[mi][ni][0], acc[mi][ni][1]);
            *(float2*)(Cs + (r1 + 8) * CSTRIDE + c0) = make_float2(acc[mi][ni][2], acc[mi][ni][3]);
        }
    }
    __syncthreads();

    const int j = j0 + lane;
    const float bs0 = bx[0 * HID + j] + bh[0 * HID + j];
    const float bs1 = bx[1 * HID + j] + bh[1 * HID + j];
    const float bs2 = bx[2 * HID + j] + bh[2 * HID + j];
    const float bs3 = bx[3 * HID + j] + bh[3 * HID + j];

#pragma unroll
    for (int i = 0; i < 16; i++) {
        const int rl  = i * 8 + wid;
        const int row = m0 + rl;
        const float4 gv = *(const float4*)(Cs + rl * CSTRIDE + lane * 4);
        const float f_ = sigm (gv.x + bs0);
        const float i_ = sigm (gv.y + bs1);
        const float c_ = tanhf(gv.z + bs2);
        const float o_ = sigm (gv.w + bs3);
        const float cv = cx[(size_t)row * HID + j];
        const float cy = f_ * cv + i_ * c_;
        const float hy = o_ * tanhf(cy);
        out[(size_t)row * HID + j] = hy;
        out[(size_t)BROWS * HID + (size_t)row * HID + j] = cy;
    }
}

extern "C" void kernel_launch(void* const* d_in, const int* in_sizes, int n_in,
                              void* d_out, int out_size)
{
    const float* x  = (const float*)d_in[0];
    const float* hx = (const float*)d_in[1];
    const float* cx = (const float*)d_in[2];
    const float* Wx = (const float*)d_in[3];
    const float* bx = (const float*)d_in[4];
    const float* Wh = (const float*)d_in[5];
    const float* bh = (const float*)d_in[6];
    float* out = (float*)d_out;

    cudaFuncSetAttribute(lstm_gemm,
                         cudaFuncAttributeMaxDynamicSharedMemorySize, SMEM_TOTAL);

    convert_a<<<dim3(8192, 2),  256>>>(x,  hx);
    convert_w<<<dim3(16384, 2), 256>>>(Wx, Wh);

    const int grid = (BROWS / BM) * NUM_NT;   // 2048
    lstm_gemm<<<grid, NTHREADS, SMEM_TOTAL>>>(cx, bx, bh, out);
}

// round 15
// speedup vs baseline: 4.1412x; 1.0045x over previous
#include <cuda_runtime.h>
#include <cuda_fp16.h>
#include <cstdint>
#include <math.h>

// ---------------- problem constants ----------------
#define HID    2048
#define BROWS  4096
#define KHALF  2048

constexpr int BM = 128;
constexpr int BN = 128;              // C cols per CTA (col = h*4+g -> 32 hidden cols)
constexpr int BK = 32;               // K per tile (2 mma k16 steps)
constexpr int NT = 4096 / BK;        // 128 k-tiles
constexpr int NPAIRS = NT / 2;       // 64
constexpr int NUM_NT = (4 * HID) / BN;  // 64 n-tiles
constexpr int GROUP_M = 8;
constexpr int NTHREADS = 256;        // 8 warps, 2 CTAs/SM

// Pre-converted fp16 tensors in the EXACT smem tile image layout.
__device__ __half g_a[16777216];     // 32 MB: [128 tiles][4096 rows][32 halfs]
__device__ __half g_w[33554432];     // 64 MB: [128 tiles][8192 cols][32 halfs]

// ---------------- smem layout (GEMM) ----------------
constexpr int TILE_BH = 8192;
constexpr int SM_A0 = 1024;                      // A: 6 slots = 48KB
constexpr int SM_B0 = SM_A0 + 6 * TILE_BH;       // B: 6 slots = 48KB
constexpr int CSTRIDE = 132;
constexpr int SM_C = 1024;
constexpr int SMEM_TOTAL = SM_B0 + 6 * TILE_BH;  // 99328

constexpr size_t A_TSTRIDE = 4096 * 64;          // bytes per A k-tile
constexpr size_t B_TSTRIDE = 8192 * 64;          // bytes per B k-tile

__device__ __forceinline__ float sigm(float v) { return 1.f / (1.f + __expf(-v)); }

__device__ __forceinline__ int perm_word(int m, int sw) {
    int w = (m & 3) * 4 + ((m >> 3) & 1) * 2 + ((m >> 2) & 1);
    return (((w >> 2) ^ sw) << 2) + (w & 3);
}

// ---------------- single merged convert kernel ----------------
// flat work units (one float4 each):
//   [0,       2M)  : x  -> g_a tiles 0..63
//   [2M,      4M)  : hx -> g_a tiles 64..127
//   [4M,      8M)  : Wx -> g_w tiles 0..63
//   [8M,     12M)  : Wh -> g_w tiles 64..127
__global__ void convert_all(const float* __restrict__ x,  const float* __restrict__ hx,
                            const float* __restrict__ Wx, const float* __restrict__ Wh)
{
    int idx = blockIdx.x * blockDim.x + threadIdx.x;   // 0 .. 12M-1
    if (idx < (4 << 20)) {
        // A path
        const float* src = (idx < (2 << 20)) ? x : hx;
        int tbase = (idx < (2 << 20)) ? 0 : 64;
        int i   = idx & ((2 << 20) - 1);
        int kq  = i & 7;
        int row = (i >> 3) & 4095;
        int t   = i >> 15;
        float4 v = *(const float4*)(src + (size_t)row * KHALF + t * BK + kq * 4);
        __half2* dst = (__half2*)(g_a + ((size_t)(tbase + t) * 4096 + row) * 32);
        int sw = (row >> 1) & 1;
        dst[perm_word(2 * kq, sw)]     = __floats2half2_rn(v.x, v.y);
        dst[perm_word(2 * kq + 1, sw)] = __floats2half2_rn(v.z, v.w);
    } else {
        // W path
        int i = idx - (4 << 20);                        // 0 .. 8M-1
        const float* src = (i < (4 << 20)) ? Wx : Wh;
        int tbase = (i < (4 << 20)) ? 0 : 64;
        i &= (4 << 20) - 1;
        int kq  = i & 7;
        int c   = (i >> 3) & 8191;
        int t   = i >> 16;
        int j = c >> 2, gate = c & 3;
        float4 v = *(const float4*)(src + (size_t)(gate * HID + j) * KHALF + t * BK + kq * 4);
        __half2* dst = (__half2*)(g_w + ((size_t)(tbase + t) * 8192 + c) * 32);
        int sw = (c >> 1) & 1;
        dst[perm_word(2 * kq, sw)]     = __floats2half2_rn(v.x, v.y);
        dst[perm_word(2 * kq + 1, sw)] = __floats2half2_rn(v.z, v.w);
    }
}

// ---------------- GEMM helpers ----------------
__device__ __forceinline__ uint32_t s2u(const void* p) {
    uint32_t a;
    asm("{ .reg .u64 t; cvta.to.shared.u64 t, %1; cvt.u32.u64 %0, t; }" : "=r"(a) : "l"(p));
    return a;
}
__device__ __forceinline__ void cpa16(uint32_t s, const void* g) {
    asm volatile("cp.async.cg.shared.global [%0], [%1], 16;" :: "r"(s), "l"(g));
}
__device__ __forceinline__ void mma_f16(float& c0, float& c1, float& c2, float& c3,
                                        uint32_t a0, uint32_t a1, uint32_t a2, uint32_t a3,
                                        uint32_t b0, uint32_t b1) {
    asm volatile(
        "mma.sync.aligned.m16n8k16.row.col.f32.f16.f16.f32 "
        "{%0,%1,%2,%3}, {%4,%5,%6,%7}, {%8,%9}, {%0,%1,%2,%3};"
        : "+f"(c0), "+f"(c1), "+f"(c2), "+f"(c3)
        : "r"(a0), "r"(a1), "r"(a2), "r"(a3), "r"(b0), "r"(b1));
}

// ---------------- GEMM + fused LSTM kernel ----------------
__global__ __launch_bounds__(NTHREADS, 2)
void lstm_gemm(const float* __restrict__ cx,
               const float* __restrict__ bx,
               const float* __restrict__ bh,
               float* __restrict__ out)
{
    extern __shared__ __align__(1024) uint8_t smem[];
    const uint32_t sbase = s2u(smem);
    const int tid  = threadIdx.x;
    const int wid  = tid >> 5;
    const int lane = tid & 31;
    const int g    = lane >> 2;
    const int tig  = lane & 3;

    // ---- CTA tile mapping ----
    int bid    = blockIdx.x;
    int group  = bid / (GROUP_M * NUM_NT);
    int rem    = bid % (GROUP_M * NUM_NT);
    int m_tile = group * GROUP_M + (rem % GROUP_M);
    int n_tile = rem / GROUP_M;
    const int m0 = m_tile * BM;
    const int j0 = n_tile * (BN / 4);

    // ---- per-thread cp.async source pointers ----
    const char* gA = (const char*)g_a + (size_t)m0 * 64 + tid * 16;
    const char* gB = (const char*)g_w + (size_t)(4 * j0) * 64 + tid * 16;

    // copy ONE tile into smem slot sl (no commit)
    auto issue_tile = [&](int sl, const char* ga, const char* gb) {
        const uint32_t sa = sbase + SM_A0 + sl * TILE_BH;
        const uint32_t sb = sbase + SM_B0 + sl * TILE_BH;
        cpa16(sa + tid * 16,        ga);
        cpa16(sa + tid * 16 + 4096, ga + 4096);
        cpa16(sb + tid * 16,        gb);
        cpa16(sb + tid * 16 + 4096, gb + 4096);
    };
    auto commit = [&]() { asm volatile("cp.async.commit_group;" ::: "memory"); };

    // ---- warp tile: 2(M) x 4(N), 64x32 per warp ----
    const int wm = (wid >> 2) * 64;
    const int wn = (wid & 3) * 32;
    const int cgo = (tig ^ ((g >> 1) & 1)) << 4;

    float acc[4][4][4];
#pragma unroll
    for (int mi = 0; mi < 4; mi++)
#pragma unroll
        for (int ni = 0; ni < 4; ni++)
#pragma unroll
            for (int q = 0; q < 4; q++) acc[mi][ni][q] = 0.f;

    auto mma_slot = [&](int sl) {
        const uint8_t* At = smem + SM_A0 + sl * TILE_BH;
        const uint8_t* Bt = smem + SM_B0 + sl * TILE_BH;
        uint4 vB[4];
#pragma unroll
        for (int ni = 0; ni < 4; ni++)
            vB[ni] = *(const uint4*)(Bt + (wn + ni * 8 + g) * 64 + cgo);
#pragma unroll
        for (int mi = 0; mi < 4; mi++) {
            uint4 vA0 = *(const uint4*)(At + (wm + mi * 16 + g)     * 64 + cgo);
            uint4 vA1 = *(const uint4*)(At + (wm + mi * 16 + g + 8) * 64 + cgo);
#pragma unroll
            for (int ni = 0; ni < 4; ni++) {
                mma_f16(acc[mi][ni][0], acc[mi][ni][1], acc[mi][ni][2], acc[mi][ni][3],
                        vA0.x, vA1.x, vA0.y, vA1.y, vB[ni].x, vB[ni].y);
                mma_f16(acc[mi][ni][0], acc[mi][ni][1], acc[mi][ni][2], acc[mi][ni][3],
                        vA0.z, vA1.z, vA0.w, vA1.w, vB[ni].z, vB[ni].w);
            }
        }
    };

    // ---- prologue: issue pairs 0 (slots 0/1) and 1 (slots 2/3) ----
    issue_tile(0, gA, gB);
    issue_tile(1, gA + A_TSTRIDE, gB + B_TSTRIDE);
    commit();
    issue_tile(2, gA + 2 * A_TSTRIDE, gB + 2 * B_TSTRIDE);
    issue_tile(3, gA + 3 * A_TSTRIDE, gB + 3 * B_TSTRIDE);
    commit();
    const char* gAn = gA + 4 * A_TSTRIDE;   // next pair to issue: pair 2
    const char* gBn = gB + 4 * B_TSTRIDE;

    // ---- mainloop: one sync per pair; copy-issue split around mma_slot ----
#pragma unroll 1
    for (int blk = 0; blk < 21; blk++) {
        const int pbase = 3 * blk;
#pragma unroll
        for (int q = 0; q < 3; q++) {
            const int p   = pbase + q;
            const int s0  = 2 * q;                    // this pair's slots
            const int sis = 2 * ((q + 2) % 3);        // issue target = (p-1)%3 slots
            asm volatile("cp.async.wait_group 1;" ::: "memory");
            __syncthreads();                          // pair p ready; p-1 fully consumed
            if (p + 2 < NPAIRS)
                issue_tile(sis, gAn, gBn);            // tile 0 of pair p+2
            mma_slot(s0);
            if (p + 2 < NPAIRS) {
                issue_tile(sis + 1, gAn + A_TSTRIDE, gBn + B_TSTRIDE);
                commit();
                gAn += 2 * A_TSTRIDE;
                gBn += 2 * B_TSTRIDE;
            }
            mma_slot(s0 + 1);
        }
    }
    // ---- tail: pair 63 (slots 0,1) ----
    asm volatile("cp.async.wait_group 0;" ::: "memory");
    __syncthreads();
    mma_slot(0);
    mma_slot(1);

    // ---- epilogue: stage C through smem, then fused LSTM math ----
    __syncthreads();
    float* Cs = (float*)(smem + SM_C);
#pragma unroll
    for (int mi = 0; mi < 4; mi++) {
#pragma unroll
        for (int ni = 0; ni < 4; ni++) {
            const int r1 = wm + mi * 16 + g;
            const int c0 = wn + ni * 8 + tig * 2;
            *(float2*)(Cs + r1 * CSTRIDE + c0)       = make_float2(acc[mi][ni][0], acc[mi][ni][1]);
            *(float2*)(Cs + (r1 + 8) * CSTRIDE + c0) = make_float2(acc[mi][ni][2], acc[mi][ni][3]);
        }
    }
    __syncthreads();

    const int j = j0 + lane;
    const float bs0 = bx[0 * HID + j] + bh[0 * HID + j];
    const float bs1 = bx[1 * HID + j] + bh[1 * HID + j];
    const float bs2 = bx[2 * HID + j] + bh[2 * HID + j];
    const float bs3 = bx[3 * HID + j] + bh[3 * HID + j];

#pragma unroll
    for (int i = 0; i < 16; i++) {
        const int rl  = i * 8 + wid;
        const int row = m0 + rl;
        const float4 gv = *(const float4*)(Cs + rl * CSTRIDE + lane * 4);
        const float f_ = sigm (gv.x + bs0);
        const float i_ = sigm (gv.y + bs1);
        const float c_ = tanhf(gv.z + bs2);
        const float o_ = sigm (gv.w + bs3);
        const float cv = cx[(size_t)row * HID + j];
        const float cy = f_ * cv + i_ * c_;
        const float hy = o_ * tanhf(cy);
        out[(size_t)row * HID + j] = hy;
        out[(size_t)BROWS * HID + (size_t)row * HID + j] = cy;
    }
}

extern "C" void kernel_launch(void* const* d_in, const int* in_sizes, int n_in,
                              void* d_out, int out_size)
{
    const float* x  = (const float*)d_in[0];
    const float* hx = (const float*)d_in[1];
    const float* cx = (const float*)d_in[2];
    const float* Wx = (const float*)d_in[3];
    const float* bx = (const float*)d_in[4];
    const float* Wh = (const float*)d_in[5];
    const float* bh = (const float*)d_in[6];
    float* out = (float*)d_out;

    cudaFuncSetAttribute(lstm_gemm,
                         cudaFuncAttributeMaxDynamicSharedMemorySize, SMEM_TOTAL);

    convert_all<<<49152, 256>>>(x, hx, Wx, Wh);   // 12M float4 units

    const int grid = (BROWS / BM) * NUM_NT;       // 2048
    lstm_gemm<<<grid, NTHREADS, SMEM_TOTAL>>>(cx, bx, bh, out);
}

// round 16
// speedup vs baseline: 4.1438x; 1.0006x over previous
#include <cuda_runtime.h>
#include <cuda_fp16.h>
#include <cstdint>
#include <math.h>

// ---------------- problem constants ----------------
#define HID    2048
#define BROWS  4096
#define KHALF  2048

constexpr int BM = 128;
constexpr int BN = 128;              // C cols per CTA (col = h*4+g -> 32 hidden cols)
constexpr int BK = 32;               // K per tile (2 mma k16 steps)
constexpr int NT = 4096 / BK;        // 128 k-tiles
constexpr int NPAIRS = NT / 2;       // 64
constexpr int NUM_NT = (4 * HID) / BN;  // 64 n-tiles
constexpr int GROUP_M = 8;
constexpr int NTHREADS = 256;        // 8 warps, 2 CTAs/SM

// Pre-converted fp16 tensors in the EXACT smem tile image layout.
__device__ __half g_a[16777216];     // 32 MB: [128 tiles][4096 rows][32 halfs]
__device__ __half g_w[33554432];     // 64 MB: [128 tiles][8192 cols][32 halfs]

// ---------------- smem layout (GEMM) ----------------
constexpr int TILE_BH = 8192;
constexpr int SM_A0 = 1024;                      // A: 6 slots = 48KB
constexpr int SM_B0 = SM_A0 + 6 * TILE_BH;       // B: 6 slots = 48KB
constexpr int CSTRIDE = 132;
constexpr int SM_C = 1024;
constexpr int SMEM_TOTAL = SM_B0 + 6 * TILE_BH;  // 99328

constexpr size_t A_TSTRIDE = 4096 * 64;          // bytes per A k-tile
constexpr size_t B_TSTRIDE = 8192 * 64;          // bytes per B k-tile

__device__ __forceinline__ float sigm(float v) { return 1.f / (1.f + __expf(-v)); }

__device__ __forceinline__ int perm_word(int m, int sw) {
    int w = (m & 3) * 4 + ((m >> 3) & 1) * 2 + ((m >> 2) & 1);
    return (((w >> 2) ^ sw) << 2) + (w & 3);
}

// ---------------- single merged convert kernel ----------------
__global__ void convert_all(const float* __restrict__ x,  const float* __restrict__ hx,
                            const float* __restrict__ Wx, const float* __restrict__ Wh)
{
    int idx = blockIdx.x * blockDim.x + threadIdx.x;   // 0 .. 12M-1
    if (idx < (4 << 20)) {
        const float* src = (idx < (2 << 20)) ? x : hx;
        int tbase = (idx < (2 << 20)) ? 0 : 64;
        int i   = idx & ((2 << 20) - 1);
        int kq  = i & 7;
        int row = (i >> 3) & 4095;
        int t   = i >> 15;
        float4 v = *(const float4*)(src + (size_t)row * KHALF + t * BK + kq * 4);
        __half2* dst = (__half2*)(g_a + ((size_t)(tbase + t) * 4096 + row) * 32);
        int sw = (row >> 1) & 1;
        dst[perm_word(2 * kq, sw)]     = __floats2half2_rn(v.x, v.y);
        dst[perm_word(2 * kq + 1, sw)] = __floats2half2_rn(v.z, v.w);
    } else {
        int i = idx - (4 << 20);
        const float* src = (i < (4 << 20)) ? Wx : Wh;
        int tbase = (i < (4 << 20)) ? 0 : 64;
        i &= (4 << 20) - 1;
        int kq  = i & 7;
        int c   = (i >> 3) & 8191;
        int t   = i >> 16;
        int j = c >> 2, gate = c & 3;
        float4 v = *(const float4*)(src + (size_t)(gate * HID + j) * KHALF + t * BK + kq * 4);
        __half2* dst = (__half2*)(g_w + ((size_t)(tbase + t) * 8192 + c) * 32);
        int sw = (c >> 1) & 1;
        dst[perm_word(2 * kq, sw)]     = __floats2half2_rn(v.x, v.y);
        dst[perm_word(2 * kq + 1, sw)] = __floats2half2_rn(v.z, v.w);
    }
}

// ---------------- GEMM helpers ----------------
__device__ __forceinline__ uint32_t s2u(const void* p) {
    uint32_t a;
    asm("{ .reg .u64 t; cvta.to.shared.u64 t, %1; cvt.u32.u64 %0, t; }" : "=r"(a) : "l"(p));
    return a;
}
__device__ __forceinline__ void cpa16(uint32_t s, const void* g) {
    asm volatile("cp.async.cg.shared.global [%0], [%1], 16;" :: "r"(s), "l"(g));
}
__device__ __forceinline__ void lds128(uint4& v, uint32_t addr) {
    asm volatile("ld.shared.v4.b32 {%0,%1,%2,%3}, [%4];"
                 : "=r"(v.x), "=r"(v.y), "=r"(v.z), "=r"(v.w) : "r"(addr));
}
__device__ __forceinline__ void mma_f16(float& c0, float& c1, float& c2, float& c3,
                                        uint32_t a0, uint32_t a1, uint32_t a2, uint32_t a3,
                                        uint32_t b0, uint32_t b1) {
    asm volatile(
        "mma.sync.aligned.m16n8k16.row.col.f32.f16.f16.f32 "
        "{%0,%1,%2,%3}, {%4,%5,%6,%7}, {%8,%9}, {%0,%1,%2,%3};"
        : "+f"(c0), "+f"(c1), "+f"(c2), "+f"(c3)
        : "r"(a0), "r"(a1), "r"(a2), "r"(a3), "r"(b0), "r"(b1));
}

// ---------------- GEMM + fused LSTM kernel ----------------
__global__ __launch_bounds__(NTHREADS, 2)
void lstm_gemm(const float* __restrict__ cx,
               const float* __restrict__ bx,
               const float* __restrict__ bh,
               float* __restrict__ out)
{
    extern __shared__ __align__(1024) uint8_t smem[];
    const uint32_t sbase = s2u(smem);
    const int tid  = threadIdx.x;
    const int wid  = tid >> 5;
    const int lane = tid & 31;
    const int g    = lane >> 2;
    const int tig  = lane & 3;

    // ---- CTA tile mapping ----
    int bid    = blockIdx.x;
    int group  = bid / (GROUP_M * NUM_NT);
    int rem    = bid % (GROUP_M * NUM_NT);
    int m_tile = group * GROUP_M + (rem % GROUP_M);
    int n_tile = rem / GROUP_M;
    const int m0 = m_tile * BM;
    const int j0 = n_tile * (BN / 4);

    // ---- hoisted bases (all mainloop addresses = base + compile-time imm) ----
    const int wm = (wid >> 2) * 64;
    const int wn = (wid & 3) * 32;
    const int cgo = (tig ^ ((g >> 1) & 1)) << 4;
    const uint32_t aAddr = sbase + SM_A0 + (uint32_t)((wm + g) * 64 + cgo);  // + sl*8192 + mi*1024 (+512)
    const uint32_t bAddr = sbase + SM_B0 + (uint32_t)((wn + g) * 64 + cgo);  // + sl*8192 + ni*512
    const uint32_t csa   = sbase + SM_A0 + (uint32_t)(tid * 16);             // + sl*8192 (+4096)
    const uint32_t csb   = sbase + SM_B0 + (uint32_t)(tid * 16);
    const char* gA = (const char*)g_a + (size_t)m0 * 64 + tid * 16;
    const char* gB = (const char*)g_w + (size_t)(4 * j0) * 64 + tid * 16;

    // copy ONE tile into smem slot sl (sl compile-time; no commit)
    auto issue_tile = [&](int sl, const char* ga, const char* gb) {
        cpa16(csa + sl * TILE_BH,        ga);
        cpa16(csa + sl * TILE_BH + 4096, ga + 4096);
        cpa16(csb + sl * TILE_BH,        gb);
        cpa16(csb + sl * TILE_BH + 4096, gb + 4096);
    };
    auto commit = [&]() { asm volatile("cp.async.commit_group;" ::: "memory"); };

    float acc[4][4][4];
#pragma unroll
    for (int mi = 0; mi < 4; mi++)
#pragma unroll
        for (int ni = 0; ni < 4; ni++)
#pragma unroll
            for (int q = 0; q < 4; q++) acc[mi][ni][q] = 0.f;

    auto mma_slot = [&](int sl) {
        uint4 vB[4];
#pragma unroll
        for (int ni = 0; ni < 4; ni++)
            lds128(vB[ni], bAddr + sl * TILE_BH + ni * 512);
#pragma unroll
        for (int mi = 0; mi < 4; mi++) {
            uint4 vA0, vA1;
            lds128(vA0, aAddr + sl * TILE_BH + mi * 1024);
            lds128(vA1, aAddr + sl * TILE_BH + mi * 1024 + 512);
#pragma unroll
            for (int ni = 0; ni < 4; ni++) {
                mma_f16(acc[mi][ni][0], acc[mi][ni][1], acc[mi][ni][2], acc[mi][ni][3],
                        vA0.x, vA1.x, vA0.y, vA1.y, vB[ni].x, vB[ni].y);
                mma_f16(acc[mi][ni][0], acc[mi][ni][1], acc[mi][ni][2], acc[mi][ni][3],
                        vA0.z, vA1.z, vA0.w, vA1.w, vB[ni].z, vB[ni].w);
            }
        }
    };

    // ---- prologue: issue pairs 0 (slots 0/1) and 1 (slots 2/3) ----
    issue_tile(0, gA, gB);
    issue_tile(1, gA + A_TSTRIDE, gB + B_TSTRIDE);
    commit();
    issue_tile(2, gA + 2 * A_TSTRIDE, gB + 2 * B_TSTRIDE);
    issue_tile(3, gA + 3 * A_TSTRIDE, gB + 3 * B_TSTRIDE);
    commit();
    const char* gAn = gA + 4 * A_TSTRIDE;   // next pair to issue: pair 2
    const char* gBn = gB + 4 * B_TSTRIDE;

    // ---- mainloop: one sync per pair; copy-issue split around mma_slot ----
#pragma unroll 1
    for (int blk = 0; blk < 21; blk++) {
        const int pbase = 3 * blk;
#pragma unroll
        for (int q = 0; q < 3; q++) {
            const int p   = pbase + q;
            const int s0  = 2 * q;                    // this pair's slots
            const int sis = 2 * ((q + 2) % 3);        // issue target = (p-1)%3 slots
            asm volatile("cp.async.wait_group 1;" ::: "memory");
            __syncthreads();                          // pair p ready; p-1 fully consumed
            if (p + 2 < NPAIRS)
                issue_tile(sis, gAn, gBn);            // tile 0 of pair p+2
            mma_slot(s0);
            if (p + 2 < NPAIRS) {
                issue_tile(sis + 1, gAn + A_TSTRIDE, gBn + B_TSTRIDE);
                commit();
                gAn += 2 * A_TSTRIDE;
                gBn += 2 * B_TSTRIDE;
            }
            mma_slot(s0 + 1);
        }
    }
    // ---- tail: pair 63 (slots 0,1) ----
    asm volatile("cp.async.wait_group 0;" ::: "memory");
    __syncthreads();
    mma_slot(0);
    mma_slot(1);

    // ---- epilogue: stage C through smem, then fused LSTM math ----
    __syncthreads();
    float* Cs = (float*)(smem + SM_C);
#pragma unroll
    for (int mi = 0; mi < 4; mi++) {
#pragma unroll
        for (int ni = 0; ni < 4; ni++) {
            const int r1 = wm + mi * 16 + g;
            const int c0 = wn + ni * 8 + tig * 2;
            *(float2*)(Cs + r1 * CSTRIDE + c0)       = make_float2(acc[mi][ni][0], acc[mi][ni][1]);
            *(float2*)(Cs + (r1 + 8) * CSTRIDE + c0) = make_float2(acc[mi][ni][2], acc[mi][ni][3]);
        }
    }
    __syncthreads();

    const int j = j0 + lane;
    const float bs0 = bx[0 * HID + j] + bh[0 * HID + j];
    const float bs1 = bx[1 * HID + j] + bh[1 * HID + j];
    const float bs2 = bx[2 * HID + j] + bh[2 * HID + j];
    const float bs3 = bx[3 * HID + j] + bh[3 * HID + j];

#pragma unroll
    for (int i = 0; i < 16; i++) {
        const int rl  = i * 8 + wid;
        const int row = m0 + rl;
        const float4 gv = *(const float4*)(Cs + rl * CSTRIDE + lane * 4);
        const float f_ = sigm (gv.x + bs0);
        const float i_ = sigm (gv.y + bs1);
        const float c_ = tanhf(gv.z + bs2);
        const float o_ = sigm (gv.w + bs3);
        const float cv = cx[(size_t)row * HID + j];
        const float cy = f_ * cv + i_ * c_;
        const float hy = o_ * tanhf(cy);
        out[(size_t)row * HID + j] = hy;
        out[(size_t)BROWS * HID + (size_t)row * HID + j] = cy;
    }
}

extern "C" void kernel_launch(void* const* d_in, const int* in_sizes, int n_in,
                              void* d_out, int out_size)
{
    const float* x  = (const float*)d_in[0];
    const float* hx = (const float*)d_in[1];
    const float* cx = (const float*)d_in[2];
    const float* Wx = (const float*)d_in[3];
    const float* bx = (const float*)d_in[4];
    const float* Wh = (const float*)d_in[5];
    const float* bh = (const float*)d_in[6];
    float* out = (float*)d_out;

    cudaFuncSetAttribute(lstm_gemm,
                         cudaFuncAttributeMaxDynamicSharedMemorySize, SMEM_TOTAL);

    convert_all<<<49152, 256>>>(x, hx, Wx, Wh);   // 12M float4 units

    const int grid = (BROWS / BM) * NUM_NT;       // 2048
    lstm_gemm<<<grid, NTHREADS, SMEM_TOTAL>>>(cx, bx, bh, out);
}